// round 2
// baseline (speedup 1.0000x reference)
#include <cuda_runtime.h>
#include <math.h>
#include <stdint.h>

#define HID 512
#define BSZ 64
#define TLEN 128
#define VOC 32000
#define G3H 1536

// ---------------- scratch (__device__ globals; no allocations allowed) ----
__device__ float g_gi[TLEN * G3H * BSZ];   // giT[t][j][b]  (encoder input gates, 50.3MB)
__device__ float g_hA[HID * BSZ];          // hT[k][b] ping
__device__ float g_hB[HID * BSZ];          // hT[k][b] pong
__device__ float g_eT[HID * BSZ];          // decoder input embedding, transposed
__device__ int   g_tok[BSZ];
__device__ unsigned long long g_amax[BSZ];

__device__ __forceinline__ unsigned ordered_f32(float f) {
    unsigned u = __float_as_uint(f);
    return (u & 0x80000000u) ? ~u : (u | 0x80000000u);
}

// ---------------- init ----------------------------------------------------
__global__ void k_init() {
    int idx = blockIdx.x * blockDim.x + threadIdx.x;
    if (idx < HID * BSZ) { g_hA[idx] = 0.f; }
    if (idx < BSZ) { g_tok[idx] = 2; g_amax[idx] = 0ull; }
}

// ---------------- SGEMM: C[m,n] = sum_k A[m,k]*W[n,k] + bias[n] -----------
// MODE 0: A gathered from embedding table via tokens; epilogue stores
//         transposed into g_gi[t][n][b] (one t per m-tile, BM==BSZ==64).
// MODE 1: A = hT (k-major, [512][64]); epilogue stores logits row-major to
//         `out`, plus packed-key atomicMax argmax into g_amax.
template<int MODE>
__global__ void __launch_bounds__(256) sgemm_k(
    const float* __restrict__ Asrc, const int* __restrict__ tokens,
    const float* __restrict__ W, const float* __restrict__ bias,
    float* __restrict__ out, int hsel)
{
    __shared__ float As[32][68];
    __shared__ float Bs[32][132];
    const int tid = threadIdx.x;
    const int tx = tid & 15, ty = tid >> 4;
    const int nblk = blockIdx.x * 128;
    const int mblk = blockIdx.y * 64;

    const int c4a = tid & 7, rowa = tid >> 3;   // MODE0 A-load mapping
    const int c4m = tid & 15, ka   = tid >> 4;  // MODE1 A-load mapping
    const int c4b = tid & 7, rowb = tid >> 3;   // B-load mapping

    const float* Ak = Asrc;
    int grow0 = 0, grow1 = 0;
    if (MODE == 0) {
        grow0 = tokens[mblk + rowa];
        grow1 = tokens[mblk + rowa + 32];
    } else {
        Ak = hsel ? g_hB : g_hA;
    }
    const float* Wb = W + (size_t)nblk * HID;

    float acc[4][8];
#pragma unroll
    for (int i = 0; i < 4; i++)
#pragma unroll
        for (int j = 0; j < 8; j++) acc[i][j] = 0.f;

    float4 aR0, aR1, bR0, bR1, bR2, bR3;

#define LDG_TILE(k0) do {                                                     \
    if (MODE == 0) {                                                          \
        aR0 = *(const float4*)(Ak + (size_t)grow0 * HID + (k0) + c4a * 4);    \
        aR1 = *(const float4*)(Ak + (size_t)grow1 * HID + (k0) + c4a * 4);    \
    } else {                                                                  \
        aR0 = *(const float4*)(Ak + (size_t)((k0) + ka)      * 64 + c4m * 4); \
        aR1 = *(const float4*)(Ak + (size_t)((k0) + ka + 16) * 64 + c4m * 4); \
    }                                                                         \
    bR0 = *(const float4*)(Wb + (size_t)(rowb      ) * HID + (k0) + c4b * 4); \
    bR1 = *(const float4*)(Wb + (size_t)(rowb +  32) * HID + (k0) + c4b * 4); \
    bR2 = *(const float4*)(Wb + (size_t)(rowb +  64) * HID + (k0) + c4b * 4); \
    bR3 = *(const float4*)(Wb + (size_t)(rowb +  96) * HID + (k0) + c4b * 4); \
} while (0)

#define STS_TILE() do {                                                       \
    if (MODE == 0) {                                                          \
        As[c4a*4+0][rowa] = aR0.x; As[c4a*4+1][rowa] = aR0.y;                 \
        As[c4a*4+2][rowa] = aR0.z; As[c4a*4+3][rowa] = aR0.w;                 \
        As[c4a*4+0][rowa+32] = aR1.x; As[c4a*4+1][rowa+32] = aR1.y;           \
        As[c4a*4+2][rowa+32] = aR1.z; As[c4a*4+3][rowa+32] = aR1.w;           \
    } else {                                                                  \
        *(float4*)&As[ka     ][c4m*4] = aR0;                                  \
        *(float4*)&As[ka + 16][c4m*4] = aR1;                                  \
    }                                                                         \
    Bs[c4b*4+0][rowb   ] = bR0.x; Bs[c4b*4+1][rowb   ] = bR0.y;               \
    Bs[c4b*4+2][rowb   ] = bR0.z; Bs[c4b*4+3][rowb   ] = bR0.w;               \
    Bs[c4b*4+0][rowb+32] = bR1.x; Bs[c4b*4+1][rowb+32] = bR1.y;               \
    Bs[c4b*4+2][rowb+32] = bR1.z; Bs[c4b*4+3][rowb+32] = bR1.w;               \
    Bs[c4b*4+0][rowb+64] = bR2.x; Bs[c4b*4+1][rowb+64] = bR2.y;               \
    Bs[c4b*4+2][rowb+64] = bR2.z; Bs[c4b*4+3][rowb+64] = bR2.w;               \
    Bs[c4b*4+0][rowb+96] = bR3.x; Bs[c4b*4+1][rowb+96] = bR3.y;               \
    Bs[c4b*4+2][rowb+96] = bR3.z; Bs[c4b*4+3][rowb+96] = bR3.w;               \
} while (0)

    LDG_TILE(0);
#pragma unroll 1
    for (int kt = 0; kt < 16; kt++) {
        __syncthreads();
        STS_TILE();
        __syncthreads();
        if (kt < 15) { LDG_TILE((kt + 1) * 32); }
#pragma unroll
        for (int k = 0; k < 32; k++) {
            float4 a  = *(const float4*)&As[k][ty * 4];
            float4 b0 = *(const float4*)&Bs[k][tx * 4];
            float4 b1 = *(const float4*)&Bs[k][64 + tx * 4];
            float av[4] = {a.x, a.y, a.z, a.w};
            float bv[8] = {b0.x, b0.y, b0.z, b0.w, b1.x, b1.y, b1.z, b1.w};
#pragma unroll
            for (int i = 0; i < 4; i++)
#pragma unroll
                for (int j = 0; j < 8; j++)
                    acc[i][j] = fmaf(av[i], bv[j], acc[i][j]);
        }
    }
#undef LDG_TILE
#undef STS_TILE

    if (MODE == 0) {
        // store transposed with bias: g_gi[(t*G3H + n)*64 + m]
        const int t = blockIdx.y;
        float* gout = g_gi + ((size_t)t * G3H + nblk) * 64;
#pragma unroll
        for (int j = 0; j < 8; j++) {
            int nl = (j < 4) ? (tx * 4 + j) : (64 + tx * 4 + (j - 4));
            float bb = bias[nblk + nl];
            float4 v = make_float4(acc[0][j] + bb, acc[1][j] + bb,
                                   acc[2][j] + bb, acc[3][j] + bb);
            *(float4*)(gout + (size_t)nl * 64 + ty * 4) = v;
        }
    } else {
        // logits: row-major store + argmax atomics
#pragma unroll
        for (int i = 0; i < 4; i++) {
            int b = ty * 4 + i;
            float* orow = out + (size_t)b * VOC + nblk;
            float v[8];
            float best = -3.4e38f;
            int bestn = 0;
#pragma unroll
            for (int j = 0; j < 8; j++) {
                int nl = (j < 4) ? (tx * 4 + j) : (64 + tx * 4 + (j - 4));
                v[j] = acc[i][j] + bias[nblk + nl];
                if (v[j] > best) { best = v[j]; bestn = nblk + nl; }
            }
            *(float4*)(orow + tx * 4)      = make_float4(v[0], v[1], v[2], v[3]);
            *(float4*)(orow + 64 + tx * 4) = make_float4(v[4], v[5], v[6], v[7]);
            unsigned long long key =
                ((unsigned long long)ordered_f32(best) << 32) |
                (unsigned long long)(0xFFFFFFFFu - (unsigned)bestn);
            atomicMax(&g_amax[b], key);
        }
    }
}

// ---------------- fused GRU gate step -------------------------------------
// ENC (DEC=0): 128 CTAs x 256 thr, 4 hidden units/CTA; gi read from g_gi[t].
// DEC (DEC=1): 256 CTAs x 128 thr, 2 hidden units/CTA; gi computed from
//              g_eT and Wih_d in the same pass (6 dot products/thread).
template<int DEC>
__global__ void gru_gate_k(
    const float* __restrict__ Wih, const float* __restrict__ bih,
    const float* __restrict__ Whh, const float* __restrict__ bhh,
    const int* __restrict__ lengths, int t, int par)
{
    constexpr int UPB = DEC ? 2 : 4;
    __shared__ float Wh[3 * UPB][HID];
    __shared__ float Wi[DEC ? 3 * UPB : 1][HID];
    const int tid = threadIdx.x;
    const int u0 = blockIdx.x * UPB;
    const int nth = 64 * UPB;

    for (int idx = tid; idx < 3 * UPB * HID; idx += nth) {
        int r = idx >> 9, k = idx & 511;
        int g = r / UPB, ui = r % UPB;
        size_t wrow = (size_t)(g * HID + u0 + ui) * HID;
        Wh[r][k] = Whh[wrow + k];
        if (DEC) Wi[r][k] = Wih[wrow + k];
    }
    __syncthreads();

    const float* hin = par ? g_hB : g_hA;
    float* hout = par ? g_hA : g_hB;
    const int b = tid & 63;
    const int ui = tid >> 6;
    const int u = u0 + ui;

    float aR = bhh[u], aZ = bhh[HID + u], aN = bhh[2 * HID + u];
    float iR, iZ, iN;
    if (DEC) {
        iR = bih[u]; iZ = bih[HID + u]; iN = bih[2 * HID + u];
    } else {
        const float* gi = g_gi + (size_t)t * (G3H * 64);
        iR = gi[(size_t)u * 64 + b];
        iZ = gi[(size_t)(HID + u) * 64 + b];
        iN = gi[(size_t)(2 * HID + u) * 64 + b];
    }

    for (int k0 = 0; k0 < HID; k0 += 8) {
        float hv[8];
#pragma unroll
        for (int kk = 0; kk < 8; kk++)
            hv[kk] = __ldg(hin + (size_t)(k0 + kk) * 64 + b);
        const float* wr = &Wh[ui][k0];
        const float* wz = &Wh[UPB + ui][k0];
        const float* wn = &Wh[2 * UPB + ui][k0];
#pragma unroll
        for (int kk = 0; kk < 8; kk++) {
            aR = fmaf(hv[kk], wr[kk], aR);
            aZ = fmaf(hv[kk], wz[kk], aZ);
            aN = fmaf(hv[kk], wn[kk], aN);
        }
        if (DEC) {
            float ev[8];
#pragma unroll
            for (int kk = 0; kk < 8; kk++)
                ev[kk] = __ldg(g_eT + (size_t)(k0 + kk) * 64 + b);
            const float* vr = &Wi[ui][k0];
            const float* vz = &Wi[UPB + ui][k0];
            const float* vn = &Wi[2 * UPB + ui][k0];
#pragma unroll
            for (int kk = 0; kk < 8; kk++) {
                iR = fmaf(ev[kk], vr[kk], iR);
                iZ = fmaf(ev[kk], vz[kk], iZ);
                iN = fmaf(ev[kk], vn[kk], iN);
            }
        }
    }

    float r = 1.f / (1.f + expf(-(iR + aR)));
    float z = 1.f / (1.f + expf(-(iZ + aZ)));
    float n = tanhf(iN + r * aN);
    float hp = hin[(size_t)u * 64 + b];
    float hn = (1.f - z) * n + z * hp;
    if (!DEC) hn = (t < lengths[b]) ? hn : hp;   // packed-sequence freeze
    hout[(size_t)u * 64 + b] = hn;
}

// ---------------- decoder embedding gather (transposed) -------------------
__global__ void k_egather(const float* __restrict__ emb_dec) {
    int b = blockIdx.x;
    int row = g_tok[b];
    const float* src = emb_dec + (size_t)row * HID;
    for (int k = threadIdx.x; k < HID; k += blockDim.x)
        g_eT[(size_t)k * 64 + b] = src[k];
}

// ---------------- argmax finalize ----------------------------------------
__global__ void k_fin() {
    int b = threadIdx.x;
    if (b < BSZ) {
        unsigned long long key = g_amax[b];
        g_tok[b] = (int)(0xFFFFFFFFu - (unsigned)(key & 0xFFFFFFFFull));
        g_amax[b] = 0ull;
    }
}

// ---------------- host orchestration --------------------------------------
extern "C" void kernel_launch(void* const* d_in, const int* in_sizes, int n_in,
                              void* d_out, int out_size) {
    const int*   batch_X = (const int*)d_in[0];
    const int*   lengths = (const int*)d_in[1];
    // d_in[2] = max_length (derived from out_size instead)
    const float* emb_enc = (const float*)d_in[3];
    const float* Wih_e   = (const float*)d_in[4];
    const float* Whh_e   = (const float*)d_in[5];
    const float* bih_e   = (const float*)d_in[6];
    const float* bhh_e   = (const float*)d_in[7];
    const float* emb_dec = (const float*)d_in[8];
    const float* Wih_d   = (const float*)d_in[9];
    const float* Whh_d   = (const float*)d_in[10];
    const float* bih_d   = (const float*)d_in[11];
    const float* bhh_d   = (const float*)d_in[12];
    const float* Wout    = (const float*)d_in[13];
    const float* bout    = (const float*)d_in[14];
    float* out = (float*)d_out;
    const int steps = out_size / (BSZ * VOC);   // 32

    (void)in_sizes; (void)n_in;

    k_init<<<128, 256>>>();

    // encoder input pre-GEMM: all timesteps at once (8192 x 1536, K=512)
    sgemm_k<0><<<dim3(G3H / 128, (TLEN * BSZ) / 64), 256>>>(
        emb_enc, batch_X, Wih_e, bih_e, nullptr, 0);

    // encoder recurrence
    for (int t = 0; t < TLEN; t++)
        gru_gate_k<0><<<HID / 4, 256>>>(nullptr, nullptr, Whh_e, bhh_e,
                                        lengths, t, t & 1);
    // final hidden ends in g_hA (128 steps, even)

    // decoder greedy loop
    for (int s = 0; s < steps; s++) {
        k_egather<<<BSZ, 128>>>(emb_dec);
        gru_gate_k<1><<<HID / 2, 128>>>(Wih_d, bih_d, Whh_d, bhh_d,
                                        nullptr, 0, s & 1);
        // h_new lives in the buffer opposite to (s&1): hsel=1 -> g_hB
        sgemm_k<1><<<dim3(VOC / 128, 1), 256>>>(
            nullptr, nullptr, Wout, bout,
            out + (size_t)s * BSZ * VOC, 1 - (s & 1));
        k_fin<<<1, 64>>>();
    }
}

// round 3
// speedup vs baseline: 1.6948x; 1.6948x over previous
#include <cuda_runtime.h>
#include <math.h>
#include <stdint.h>

#define HID 512
#define BSZ 64
#define TLEN 128
#define VOC 32000
#define G3H 1536
#define ENC_CTAS 128

// ---------------- scratch (__device__ globals; no allocations allowed) ----
__device__ float g_gi[TLEN * G3H * BSZ];   // giT[t][j][b]  (encoder input gates)
__device__ float g_hA[HID * BSZ];          // hT[k][b] ping
__device__ float g_hB[HID * BSZ];          // hT[k][b] pong
__device__ float g_eT[HID * BSZ];          // decoder input embedding, transposed
__device__ unsigned long long g_amax[BSZ];
__device__ unsigned g_bar_cnt;
__device__ unsigned g_bar_rel;

__device__ __forceinline__ unsigned ordered_f32(float f) {
    unsigned u = __float_as_uint(f);
    return (u & 0x80000000u) ? ~u : (u | 0x80000000u);
}

// ---------------- init ----------------------------------------------------
__global__ void k_init(const float* __restrict__ emb_dec) {
    int idx = blockIdx.x * blockDim.x + threadIdx.x;   // 0..32767
    if (idx < HID * BSZ) {
        g_hA[idx] = 0.f;
        g_eT[idx] = emb_dec[2 * HID + (idx >> 6)];     // BOS embedding, transposed
    }
    if (idx < BSZ) g_amax[idx] = 0ull;
    if (idx == 0) { g_bar_cnt = 0u; g_bar_rel = 0u; }
}

// ---------------- SGEMM: C[m,n] = sum_k A[m,k]*W[n,k] + bias[n] -----------
// MODE 0: A gathered from embedding table via tokens; epilogue stores
//         transposed into g_gi[t][n][b] (one t per m-tile, BM==BSZ==64).
// MODE 1: A = hT (k-major, [512][64]); epilogue stores logits row-major to
//         `out`, plus packed-key atomicMax argmax into g_amax.
template<int MODE>
__global__ void __launch_bounds__(256) sgemm_k(
    const float* __restrict__ Asrc, const int* __restrict__ tokens,
    const float* __restrict__ W, const float* __restrict__ bias,
    float* __restrict__ out, int hsel)
{
    __shared__ float As[32][68];
    __shared__ float Bs[32][132];
    const int tid = threadIdx.x;
    const int tx = tid & 15, ty = tid >> 4;
    const int nblk = blockIdx.x * 128;
    const int mblk = blockIdx.y * 64;

    const int c4a = tid & 7, rowa = tid >> 3;   // MODE0 A-load mapping
    const int c4m = tid & 15, ka   = tid >> 4;  // MODE1 A-load mapping
    const int c4b = tid & 7, rowb = tid >> 3;   // B-load mapping

    const float* Ak = Asrc;
    int grow0 = 0, grow1 = 0;
    if (MODE == 0) {
        grow0 = tokens[mblk + rowa];
        grow1 = tokens[mblk + rowa + 32];
    } else {
        Ak = hsel ? g_hB : g_hA;
    }
    const float* Wb = W + (size_t)nblk * HID;

    float acc[4][8];
#pragma unroll
    for (int i = 0; i < 4; i++)
#pragma unroll
        for (int j = 0; j < 8; j++) acc[i][j] = 0.f;

    float4 aR0, aR1, bR0, bR1, bR2, bR3;

#define LDG_TILE(k0) do {                                                     \
    if (MODE == 0) {                                                          \
        aR0 = *(const float4*)(Ak + (size_t)grow0 * HID + (k0) + c4a * 4);    \
        aR1 = *(const float4*)(Ak + (size_t)grow1 * HID + (k0) + c4a * 4);    \
    } else {                                                                  \
        aR0 = *(const float4*)(Ak + (size_t)((k0) + ka)      * 64 + c4m * 4); \
        aR1 = *(const float4*)(Ak + (size_t)((k0) + ka + 16) * 64 + c4m * 4); \
    }                                                                         \
    bR0 = *(const float4*)(Wb + (size_t)(rowb      ) * HID + (k0) + c4b * 4); \
    bR1 = *(const float4*)(Wb + (size_t)(rowb +  32) * HID + (k0) + c4b * 4); \
    bR2 = *(const float4*)(Wb + (size_t)(rowb +  64) * HID + (k0) + c4b * 4); \
    bR3 = *(const float4*)(Wb + (size_t)(rowb +  96) * HID + (k0) + c4b * 4); \
} while (0)

#define STS_TILE() do {                                                       \
    if (MODE == 0) {                                                          \
        As[c4a*4+0][rowa] = aR0.x; As[c4a*4+1][rowa] = aR0.y;                 \
        As[c4a*4+2][rowa] = aR0.z; As[c4a*4+3][rowa] = aR0.w;                 \
        As[c4a*4+0][rowa+32] = aR1.x; As[c4a*4+1][rowa+32] = aR1.y;           \
        As[c4a*4+2][rowa+32] = aR1.z; As[c4a*4+3][rowa+32] = aR1.w;           \
    } else {                                                                  \
        *(float4*)&As[ka     ][c4m*4] = aR0;                                  \
        *(float4*)&As[ka + 16][c4m*4] = aR1;                                  \
    }                                                                         \
    Bs[c4b*4+0][rowb   ] = bR0.x; Bs[c4b*4+1][rowb   ] = bR0.y;               \
    Bs[c4b*4+2][rowb   ] = bR0.z; Bs[c4b*4+3][rowb   ] = bR0.w;               \
    Bs[c4b*4+0][rowb+32] = bR1.x; Bs[c4b*4+1][rowb+32] = bR1.y;               \
    Bs[c4b*4+2][rowb+32] = bR1.z; Bs[c4b*4+3][rowb+32] = bR1.w;               \
    Bs[c4b*4+0][rowb+64] = bR2.x; Bs[c4b*4+1][rowb+64] = bR2.y;               \
    Bs[c4b*4+2][rowb+64] = bR2.z; Bs[c4b*4+3][rowb+64] = bR2.w;               \
    Bs[c4b*4+0][rowb+96] = bR3.x; Bs[c4b*4+1][rowb+96] = bR3.y;               \
    Bs[c4b*4+2][rowb+96] = bR3.z; Bs[c4b*4+3][rowb+96] = bR3.w;               \
} while (0)

    LDG_TILE(0);
#pragma unroll 1
    for (int kt = 0; kt < 16; kt++) {
        __syncthreads();
        STS_TILE();
        __syncthreads();
        if (kt < 15) { LDG_TILE((kt + 1) * 32); }
#pragma unroll
        for (int k = 0; k < 32; k++) {
            float4 a  = *(const float4*)&As[k][ty * 4];
            float4 b0 = *(const float4*)&Bs[k][tx * 4];
            float4 b1 = *(const float4*)&Bs[k][64 + tx * 4];
            float av[4] = {a.x, a.y, a.z, a.w};
            float bv[8] = {b0.x, b0.y, b0.z, b0.w, b1.x, b1.y, b1.z, b1.w};
#pragma unroll
            for (int i = 0; i < 4; i++)
#pragma unroll
                for (int j = 0; j < 8; j++)
                    acc[i][j] = fmaf(av[i], bv[j], acc[i][j]);
        }
    }
#undef LDG_TILE
#undef STS_TILE

    if (MODE == 0) {
        const int t = blockIdx.y;
        float* gout = g_gi + ((size_t)t * G3H + nblk) * 64;
#pragma unroll
        for (int j = 0; j < 8; j++) {
            int nl = (j < 4) ? (tx * 4 + j) : (64 + tx * 4 + (j - 4));
            float bb = bias[nblk + nl];
            float4 v = make_float4(acc[0][j] + bb, acc[1][j] + bb,
                                   acc[2][j] + bb, acc[3][j] + bb);
            *(float4*)(gout + (size_t)nl * 64 + ty * 4) = v;
        }
    } else {
#pragma unroll
        for (int i = 0; i < 4; i++) {
            int b = ty * 4 + i;
            float* orow = out + (size_t)b * VOC + nblk;
            float v[8];
            float best = -3.4e38f;
            int bestn = 0;
#pragma unroll
            for (int j = 0; j < 8; j++) {
                int nl = (j < 4) ? (tx * 4 + j) : (64 + tx * 4 + (j - 4));
                v[j] = acc[i][j] + bias[nblk + nl];
                if (v[j] > best) { best = v[j]; bestn = nblk + nl; }
            }
            *(float4*)(orow + tx * 4)      = make_float4(v[0], v[1], v[2], v[3]);
            *(float4*)(orow + 64 + tx * 4) = make_float4(v[4], v[5], v[6], v[7]);
            unsigned long long key =
                ((unsigned long long)ordered_f32(best) << 32) |
                (unsigned long long)(0xFFFFFFFFu - (unsigned)bestn);
            atomicMax(&g_amax[b], key);
        }
    }
}

// ---------------- persistent encoder recurrence ----------------------------
// 128 CTAs x 256 threads, all resident (<=148 SMs). Whh staged to smem ONCE.
// h ping-pongs via global (__ldcg to bypass L1 staleness across steps);
// per-step release via fenced atomic grid barrier.
__global__ void __launch_bounds__(256, 1) enc_persist_k(
    const float* __restrict__ Whh, const float* __restrict__ bhh,
    const int* __restrict__ lengths)
{
    __shared__ float Wh[12][HID];   // rows: g*4 + ui   (24KB)
    const int tid = threadIdx.x;
    const int u0 = blockIdx.x * 4;

    for (int idx = tid; idx < 12 * HID; idx += 256) {
        int r = idx >> 9, k = idx & 511;
        int g = r >> 2, ui = r & 3;
        Wh[r][k] = Whh[(size_t)(g * HID + u0 + ui) * HID + k];
    }
    const int b  = tid & 63;
    const int ui = tid >> 6;
    const int u  = u0 + ui;
    const float bR = bhh[u], bZ = bhh[HID + u], bN = bhh[2 * HID + u];
    const int len = lengths[b];
    __syncthreads();

#pragma unroll 1
    for (int t = 0; t < TLEN; t++) {
        const float* hin = (t & 1) ? g_hB : g_hA;
        float* hout      = (t & 1) ? g_hA : g_hB;
        const float* gi  = g_gi + (size_t)t * (G3H * 64);

        float aR = bR + gi[(size_t)u * 64 + b];
        float aZ = bZ + gi[(size_t)(HID + u) * 64 + b];
        float aN = bN + gi[(size_t)(2 * HID + u) * 64 + b];

        float hv[16];
#pragma unroll
        for (int kk = 0; kk < 16; kk++) hv[kk] = __ldcg(hin + kk * 64 + b);

#pragma unroll 2
        for (int k0 = 0; k0 < HID; k0 += 16) {
            float nv[16];
            const int kn = (k0 + 16 < HID) ? (k0 + 16) : 0;  // last prefetch dummy
#pragma unroll
            for (int kk = 0; kk < 16; kk++)
                nv[kk] = __ldcg(hin + (kn + kk) * 64 + b);
            const float4* wr = (const float4*)&Wh[ui][k0];
            const float4* wz = (const float4*)&Wh[4 + ui][k0];
            const float4* wn = (const float4*)&Wh[8 + ui][k0];
#pragma unroll
            for (int q = 0; q < 4; q++) {
                float4 r4 = wr[q], z4 = wz[q], n4 = wn[q];
                aR = fmaf(hv[q*4+0], r4.x, aR); aR = fmaf(hv[q*4+1], r4.y, aR);
                aR = fmaf(hv[q*4+2], r4.z, aR); aR = fmaf(hv[q*4+3], r4.w, aR);
                aZ = fmaf(hv[q*4+0], z4.x, aZ); aZ = fmaf(hv[q*4+1], z4.y, aZ);
                aZ = fmaf(hv[q*4+2], z4.z, aZ); aZ = fmaf(hv[q*4+3], z4.w, aZ);
                aN = fmaf(hv[q*4+0], n4.x, aN); aN = fmaf(hv[q*4+1], n4.y, aN);
                aN = fmaf(hv[q*4+2], n4.z, aN); aN = fmaf(hv[q*4+3], n4.w, aN);
            }
#pragma unroll
            for (int kk = 0; kk < 16; kk++) hv[kk] = nv[kk];
        }

        float r = 1.f / (1.f + expf(-aR));
        float z = 1.f / (1.f + expf(-aZ));
        float n = tanhf(aN - aN + (aN));   // keep aN; tanhf(aN) after r*: fix below
        n = tanhf(fmaf(r, 0.f, aN));       // placeholder removed below
        // NOTE: gh_n needs r * (h-part). aN currently = bN + gi_n + h.Whh_n,
        // but reference is  n = tanh(gi_n + r * (bhh_n + h.Whh_n)).
        // We therefore split: recompute using separate accumulation.
        (void)n;
        float hp = __ldcg(hin + (size_t)u * 64 + b);
        // --- correct gate combine (see accumulator split below) ---
        float hn = hp; // overwritten
        hn = hp; (void)hn;
        // real computation done in second pass variables:
        hout[(size_t)u * 64 + b] = 0.f; // overwritten below
        // (dead code eliminated in final version)
        // ---- actual combine ----
        {
            // aN here == bN + gi_n + (h.Whh_n)  -> need gi_n + r*(bN + h.Whh_n)
            // reconstruct: giN = gi[...] loaded above; hWn = aN - bN - giN
            float giN = g_gi[(size_t)t * (G3H * 64) + (size_t)(2 * HID + u) * 64 + b];
            float hWn = aN - bN - giN;
            float nn = tanhf(giN + r * (bN + hWn));
            float hv2 = (1.f - z) * nn + z * hp;
            if (t >= len) hv2 = hp;
            hout[(size_t)u * 64 + b] = hv2;
        }

        if (t < TLEN - 1) {
            __threadfence();
            __syncthreads();
            if (tid == 0) {
                unsigned v = atomicAdd(&g_bar_cnt, 1u);
                if (v == ENC_CTAS - 1) {
                    atomicExch(&g_bar_cnt, 0u);
                    atomicAdd(&g_bar_rel, 1u);
                }
                while (atomicAdd(&g_bar_rel, 0u) < (unsigned)(t + 1)) {}
            }
            __syncthreads();
        }
    }
}

// ---------------- fused decoder GRU step (per-launch) ----------------------
// 128 CTAs x 256 thr, 4 units/CTA; Wih+Whh staged to smem (48KB).
__global__ void __launch_bounds__(256, 1) dec_gru_k(
    const float* __restrict__ Wih, const float* __restrict__ bih,
    const float* __restrict__ Whh, const float* __restrict__ bhh, int par)
{
    __shared__ float Wh[12][HID];
    __shared__ float Wi[12][HID];
    const int tid = threadIdx.x;
    const int u0 = blockIdx.x * 4;

    for (int idx = tid; idx < 12 * HID; idx += 256) {
        int r = idx >> 9, k = idx & 511;
        int g = r >> 2, ui = r & 3;
        size_t wrow = (size_t)(g * HID + u0 + ui) * HID + k;
        Wh[r][k] = Whh[wrow];
        Wi[r][k] = Wih[wrow];
    }
    const int b  = tid & 63;
    const int ui = tid >> 6;
    const int u  = u0 + ui;
    const float bhR = bhh[u], bhZ = bhh[HID + u], bhN = bhh[2 * HID + u];
    float iR = bih[u], iZ = bih[HID + u], iN = bih[2 * HID + u];
    float hR = 0.f, hZ = 0.f, hN = 0.f;
    __syncthreads();

    const float* hin = par ? g_hB : g_hA;
    float* hout      = par ? g_hA : g_hB;

#pragma unroll 2
    for (int k0 = 0; k0 < HID; k0 += 16) {
        float hv[16], ev[16];
#pragma unroll
        for (int kk = 0; kk < 16; kk++) {
            hv[kk] = __ldg(hin  + (size_t)(k0 + kk) * 64 + b);
            ev[kk] = __ldg(g_eT + (size_t)(k0 + kk) * 64 + b);
        }
        const float4* wr = (const float4*)&Wh[ui][k0];
        const float4* wz = (const float4*)&Wh[4 + ui][k0];
        const float4* wn = (const float4*)&Wh[8 + ui][k0];
        const float4* vr = (const float4*)&Wi[ui][k0];
        const float4* vz = (const float4*)&Wi[4 + ui][k0];
        const float4* vn = (const float4*)&Wi[8 + ui][k0];
#pragma unroll
        for (int q = 0; q < 4; q++) {
            float4 r4 = wr[q], z4 = wz[q], n4 = wn[q];
            float4 s4 = vr[q], t4 = vz[q], u4 = vn[q];
#pragma unroll
            for (int e = 0; e < 4; e++) {
                float hvv = hv[q * 4 + e], evv = ev[q * 4 + e];
                float rw = (e==0)?r4.x:(e==1)?r4.y:(e==2)?r4.z:r4.w;
                float zw = (e==0)?z4.x:(e==1)?z4.y:(e==2)?z4.z:z4.w;
                float nw = (e==0)?n4.x:(e==1)?n4.y:(e==2)?n4.z:n4.w;
                float sw = (e==0)?s4.x:(e==1)?s4.y:(e==2)?s4.z:s4.w;
                float tw = (e==0)?t4.x:(e==1)?t4.y:(e==2)?t4.z:t4.w;
                float uw = (e==0)?u4.x:(e==1)?u4.y:(e==2)?u4.z:u4.w;
                hR = fmaf(hvv, rw, hR);
                hZ = fmaf(hvv, zw, hZ);
                hN = fmaf(hvv, nw, hN);
                iR = fmaf(evv, sw, iR);
                iZ = fmaf(evv, tw, iZ);
                iN = fmaf(evv, uw, iN);
            }
        }
    }

    float r = 1.f / (1.f + expf(-(iR + bhR + hR)));
    float z = 1.f / (1.f + expf(-(iZ + bhZ + hZ)));
    float n = tanhf(iN + r * (bhN + hN));
    float hp = hin[(size_t)u * 64 + b];
    hout[(size_t)u * 64 + b] = (1.f - z) * n + z * hp;
}

// ---------------- argmax finalize + next-token embedding gather -----------
__global__ void k_fin_gather(const float* __restrict__ emb_dec) {
    int b = blockIdx.x;                  // 64 CTAs x 128 threads
    __shared__ int stok;
    if (threadIdx.x == 0) {
        unsigned long long key = g_amax[b];
        stok = (int)(0xFFFFFFFFu - (unsigned)(key & 0xFFFFFFFFull));
        g_amax[b] = 0ull;
    }
    __syncthreads();
    const float* src = emb_dec + (size_t)stok * HID;
    for (int k = threadIdx.x; k < HID; k += 128)
        g_eT[(size_t)k * 64 + b] = src[k];
}

// ---------------- host orchestration --------------------------------------
extern "C" void kernel_launch(void* const* d_in, const int* in_sizes, int n_in,
                              void* d_out, int out_size) {
    const int*   batch_X = (const int*)d_in[0];
    const int*   lengths = (const int*)d_in[1];
    const float* emb_enc = (const float*)d_in[3];
    const float* Wih_e   = (const float*)d_in[4];
    const float* Whh_e   = (const float*)d_in[5];
    const float* bih_e   = (const float*)d_in[6];
    const float* bhh_e   = (const float*)d_in[7];
    const float* emb_dec = (const float*)d_in[8];
    const float* Wih_d   = (const float*)d_in[9];
    const float* Whh_d   = (const float*)d_in[10];
    const float* bih_d   = (const float*)d_in[11];
    const float* bhh_d   = (const float*)d_in[12];
    const float* Wout    = (const float*)d_in[13];
    const float* bout    = (const float*)d_in[14];
    float* out = (float*)d_out;
    const int steps = out_size / (BSZ * VOC);   // 32

    (void)in_sizes; (void)n_in;

    k_init<<<128, 256>>>(emb_dec);

    // encoder input pre-GEMM: all timesteps at once (8192 x 1536, K=512)
    sgemm_k<0><<<dim3(G3H / 128, (TLEN * BSZ) / 64), 256>>>(
        emb_enc, batch_X, Wih_e, bih_e, nullptr, 0);

    // encoder recurrence: single persistent kernel, 128 steps internally
    enc_persist_k<<<ENC_CTAS, 256>>>(Whh_e, bhh_e, lengths);
    // final hidden ends in g_hA (t=127 writes g_hA)

    // decoder greedy loop
    for (int s = 0; s < steps; s++) {
        dec_gru_k<<<HID / 4, 256>>>(Wih_d, bih_d, Whh_d, bhh_d, s & 1);
        sgemm_k<1><<<dim3(VOC / 128, 1), 256>>>(
            nullptr, nullptr, Wout, bout,
            out + (size_t)s * BSZ * VOC, 1 - (s & 1));
        if (s < steps - 1) k_fin_gather<<<BSZ, 128>>>(emb_dec);
    }
}

// round 6
// speedup vs baseline: 2.4073x; 1.4204x over previous
#include <cuda_runtime.h>
#include <cuda_bf16.h>
#include <math.h>
#include <stdint.h>

#define HID 512
#define BSZ 64
#define TLEN 128
#define VOC 32000
#define G3H 1536
#define ENC_CTAS 128

// logits GEMM tiling
#define LG_NT 256                 // vocab cols per CTA
#define LG_CTAS (VOC / LG_NT)     // 125
#define KC 32                     // k per chunk
#define ROWB 80                   // smem row stride (64B data + 16B pad, conflict-free)
#define B_ROWS (3 * LG_NT)        // 768
#define A_ROWS (3 * BSZ)          // 192
#define SBUF ((B_ROWS + A_ROWS) * ROWB)   // 76800 per buffer
#define A_OFF (B_ROWS * ROWB)             // 61440
#define LG_SMEM (2 * SBUF)                // 153600

// ---------------- scratch (__device__ globals; no allocations allowed) ----
__device__ float g_gi[TLEN * G3H * BSZ];   // giT[t][j][b]
__device__ float g_hA[HID * BSZ];          // hT[k][b] ping
__device__ float g_hB[HID * BSZ];          // hT[k][b] pong
__device__ float g_eT[HID * BSZ];          // decoder input embedding, transposed
__device__ __align__(16) unsigned short g_W1[VOC * HID];  // bf16 splits of Wout
__device__ __align__(16) unsigned short g_W2[VOC * HID];
__device__ __align__(16) unsigned short g_W3[VOC * HID];
__device__ __align__(16) unsigned short g_h1[BSZ * HID];  // bf16 splits of h, [b][k]
__device__ __align__(16) unsigned short g_h2[BSZ * HID];
__device__ __align__(16) unsigned short g_h3[BSZ * HID];
__device__ unsigned long long g_amax[BSZ];
__device__ unsigned g_bar_cnt;
__device__ unsigned g_bar_rel;

__device__ __forceinline__ unsigned ordered_f32(float f) {
    unsigned u = __float_as_uint(f);
    return (u & 0x80000000u) ? ~u : (u | 0x80000000u);
}
__device__ __forceinline__ unsigned short f2bf(float x) {
    __nv_bfloat16 t = __float2bfloat16(x);
    return *(unsigned short*)&t;
}
__device__ __forceinline__ float bf2f(unsigned short u) {
    __nv_bfloat16 t = *(__nv_bfloat16*)&u;
    return __bfloat162float(t);
}
__device__ __forceinline__ uint32_t smem_u32(const void* p) {
    uint32_t a;
    asm("{ .reg .u64 t; cvta.to.shared.u64 t, %1; cvt.u32.u64 %0, t; }"
        : "=r"(a) : "l"(p));
    return a;
}
__device__ __forceinline__ unsigned long long pack_key(float v, int idx) {
    return ((unsigned long long)ordered_f32(v) << 32) |
           (unsigned long long)(0xFFFFFFFFu - (unsigned)idx);
}

#define MMA16816(C, A0, A1, A2, A3, B0, B1) \
    asm volatile("mma.sync.aligned.m16n8k16.row.col.f32.bf16.bf16.f32 " \
        "{%0,%1,%2,%3}, {%4,%5,%6,%7}, {%8,%9}, {%0,%1,%2,%3};" \
        : "+f"((C)[0]), "+f"((C)[1]), "+f"((C)[2]), "+f"((C)[3]) \
        : "r"(A0), "r"(A1), "r"(A2), "r"(A3), "r"(B0), "r"(B1))

// ---------------- init ----------------------------------------------------
__global__ void k_init(const float* __restrict__ emb_dec) {
    int idx = blockIdx.x * blockDim.x + threadIdx.x;   // 0..32767
    if (idx < HID * BSZ) {
        g_hA[idx] = 0.f;
        g_eT[idx] = emb_dec[2 * HID + (idx >> 6)];     // BOS embedding, transposed
    }
    if (idx < BSZ) g_amax[idx] = 0ull;
    if (idx == 0) { g_bar_cnt = 0u; g_bar_rel = 0u; }
}

// ---------------- Wout -> 3-way bf16 split --------------------------------
__global__ void k_wsplit(const float* __restrict__ W) {
    size_t i = ((size_t)blockIdx.x * 256 + threadIdx.x) * 4;
    if (i >= (size_t)VOC * HID) return;
    float4 v = *(const float4*)(W + i);
    float a[4] = {v.x, v.y, v.z, v.w};
#pragma unroll
    for (int j = 0; j < 4; j++) {
        unsigned short s1 = f2bf(a[j]);
        float r1 = a[j] - bf2f(s1);
        unsigned short s2 = f2bf(r1);
        float r2 = r1 - bf2f(s2);
        unsigned short s3 = f2bf(r2);
        g_W1[i + j] = s1; g_W2[i + j] = s2; g_W3[i + j] = s3;
    }
}

// ---------------- SGEMM: encoder input pre-GEMM ---------------------------
__global__ void __launch_bounds__(256) sgemm0_k(
    const float* __restrict__ Asrc, const int* __restrict__ tokens,
    const float* __restrict__ W, const float* __restrict__ bias)
{
    __shared__ float As[32][68];
    __shared__ float Bs[32][132];
    const int tid = threadIdx.x;
    const int tx = tid & 15, ty = tid >> 4;
    const int nblk = blockIdx.x * 128;
    const int mblk = blockIdx.y * 64;

    const int c4a = tid & 7, rowa = tid >> 3;
    const int c4b = tid & 7, rowb = tid >> 3;

    const int grow0 = tokens[mblk + rowa];
    const int grow1 = tokens[mblk + rowa + 32];
    const float* Wb = W + (size_t)nblk * HID;

    float acc[4][8];
#pragma unroll
    for (int i = 0; i < 4; i++)
#pragma unroll
        for (int j = 0; j < 8; j++) acc[i][j] = 0.f;

    float4 aR0, aR1, bR0, bR1, bR2, bR3;

#define LDG_TILE(k0) do {                                                     \
    aR0 = *(const float4*)(Asrc + (size_t)grow0 * HID + (k0) + c4a * 4);      \
    aR1 = *(const float4*)(Asrc + (size_t)grow1 * HID + (k0) + c4a * 4);      \
    bR0 = *(const float4*)(Wb + (size_t)(rowb      ) * HID + (k0) + c4b * 4); \
    bR1 = *(const float4*)(Wb + (size_t)(rowb +  32) * HID + (k0) + c4b * 4); \
    bR2 = *(const float4*)(Wb + (size_t)(rowb +  64) * HID + (k0) + c4b * 4); \
    bR3 = *(const float4*)(Wb + (size_t)(rowb +  96) * HID + (k0) + c4b * 4); \
} while (0)

#define STS_TILE() do {                                                       \
    As[c4a*4+0][rowa] = aR0.x; As[c4a*4+1][rowa] = aR0.y;                     \
    As[c4a*4+2][rowa] = aR0.z; As[c4a*4+3][rowa] = aR0.w;                     \
    As[c4a*4+0][rowa+32] = aR1.x; As[c4a*4+1][rowa+32] = aR1.y;               \
    As[c4a*4+2][rowa+32] = aR1.z; As[c4a*4+3][rowa+32] = aR1.w;               \
    Bs[c4b*4+0][rowb   ] = bR0.x; Bs[c4b*4+1][rowb   ] = bR0.y;               \
    Bs[c4b*4+2][rowb   ] = bR0.z; Bs[c4b*4+3][rowb   ] = bR0.w;               \
    Bs[c4b*4+0][rowb+32] = bR1.x; Bs[c4b*4+1][rowb+32] = bR1.y;               \
    Bs[c4b*4+2][rowb+32] = bR1.z; Bs[c4b*4+3][rowb+32] = bR1.w;               \
    Bs[c4b*4+0][rowb+64] = bR2.x; Bs[c4b*4+1][rowb+64] = bR2.y;               \
    Bs[c4b*4+2][rowb+64] = bR2.z; Bs[c4b*4+3][rowb+64] = bR2.w;               \
    Bs[c4b*4+0][rowb+96] = bR3.x; Bs[c4b*4+1][rowb+96] = bR3.y;               \
    Bs[c4b*4+2][rowb+96] = bR3.z; Bs[c4b*4+3][rowb+96] = bR3.w;               \
} while (0)

    LDG_TILE(0);
#pragma unroll 1
    for (int kt = 0; kt < 16; kt++) {
        __syncthreads();
        STS_TILE();
        __syncthreads();
        if (kt < 15) { LDG_TILE((kt + 1) * 32); }
#pragma unroll
        for (int k = 0; k < 32; k++) {
            float4 a  = *(const float4*)&As[k][ty * 4];
            float4 b0 = *(const float4*)&Bs[k][tx * 4];
            float4 b1 = *(const float4*)&Bs[k][64 + tx * 4];
            float av[4] = {a.x, a.y, a.z, a.w};
            float bv[8] = {b0.x, b0.y, b0.z, b0.w, b1.x, b1.y, b1.z, b1.w};
#pragma unroll
            for (int i = 0; i < 4; i++)
#pragma unroll
                for (int j = 0; j < 8; j++)
                    acc[i][j] = fmaf(av[i], bv[j], acc[i][j]);
        }
    }
#undef LDG_TILE
#undef STS_TILE

    const int t = blockIdx.y;
    float* gout = g_gi + ((size_t)t * G3H + nblk) * 64;
#pragma unroll
    for (int j = 0; j < 8; j++) {
        int nl = (j < 4) ? (tx * 4 + j) : (64 + tx * 4 + (j - 4));
        float bb = bias[nblk + nl];
        float4 v = make_float4(acc[0][j] + bb, acc[1][j] + bb,
                               acc[2][j] + bb, acc[3][j] + bb);
        *(float4*)(gout + (size_t)nl * 64 + ty * 4) = v;
    }
}

// ---------------- persistent encoder recurrence ----------------------------
__global__ void __launch_bounds__(256, 1) enc_persist_k(
    const float* __restrict__ Whh, const float* __restrict__ bhh,
    const int* __restrict__ lengths)
{
    __shared__ float Wh[12][HID];   // rows: g*4 + ui   (24KB)
    const int tid = threadIdx.x;
    const int u0 = blockIdx.x * 4;

    for (int idx = tid; idx < 12 * HID; idx += 256) {
        int r = idx >> 9, k = idx & 511;
        int g = r >> 2, ui = r & 3;
        Wh[r][k] = Whh[(size_t)(g * HID + u0 + ui) * HID + k];
    }
    const int b  = tid & 63;
    const int ui = tid >> 6;
    const int u  = u0 + ui;
    const float bR = bhh[u], bZ = bhh[HID + u], bN = bhh[2 * HID + u];
    const int len = lengths[b];
    __syncthreads();

#pragma unroll 1
    for (int t = 0; t < TLEN; t++) {
        const float* hin = (t & 1) ? g_hB : g_hA;
        float* hout      = (t & 1) ? g_hA : g_hB;
        const float* gi  = g_gi + (size_t)t * (G3H * 64);

        float giR = gi[(size_t)u * 64 + b];
        float giZ = gi[(size_t)(HID + u) * 64 + b];
        float giN = gi[(size_t)(2 * HID + u) * 64 + b];
        float hR = 0.f, hZ = 0.f, hN = 0.f;

        float hv[16];
#pragma unroll
        for (int kk = 0; kk < 16; kk++) hv[kk] = __ldcg(hin + kk * 64 + b);

#pragma unroll 2
        for (int k0 = 0; k0 < HID; k0 += 16) {
            float nv[16];
            const int kn = (k0 + 16 < HID) ? (k0 + 16) : 0;
#pragma unroll
            for (int kk = 0; kk < 16; kk++)
                nv[kk] = __ldcg(hin + (kn + kk) * 64 + b);
            const float4* wr = (const float4*)&Wh[ui][k0];
            const float4* wz = (const float4*)&Wh[4 + ui][k0];
            const float4* wn = (const float4*)&Wh[8 + ui][k0];
#pragma unroll
            for (int q = 0; q < 4; q++) {
                float4 r4 = wr[q], z4 = wz[q], n4 = wn[q];
                hR = fmaf(hv[q*4+0], r4.x, hR); hR = fmaf(hv[q*4+1], r4.y, hR);
                hR = fmaf(hv[q*4+2], r4.z, hR); hR = fmaf(hv[q*4+3], r4.w, hR);
                hZ = fmaf(hv[q*4+0], z4.x, hZ); hZ = fmaf(hv[q*4+1], z4.y, hZ);
                hZ = fmaf(hv[q*4+2], z4.z, hZ); hZ = fmaf(hv[q*4+3], z4.w, hZ);
                hN = fmaf(hv[q*4+0], n4.x, hN); hN = fmaf(hv[q*4+1], n4.y, hN);
                hN = fmaf(hv[q*4+2], n4.z, hN); hN = fmaf(hv[q*4+3], n4.w, hN);
            }
#pragma unroll
            for (int kk = 0; kk < 16; kk++) hv[kk] = nv[kk];
        }

        float r = 1.f / (1.f + expf(-(giR + bR + hR)));
        float z = 1.f / (1.f + expf(-(giZ + bZ + hZ)));
        float n = tanhf(giN + r * (bN + hN));
        float hp = __ldcg(hin + (size_t)u * 64 + b);
        float hn = (1.f - z) * n + z * hp;
        if (t >= len) hn = hp;
        hout[(size_t)u * 64 + b] = hn;

        if (t < TLEN - 1) {
            __threadfence();
            __syncthreads();
            if (tid == 0) {
                unsigned v = atomicAdd(&g_bar_cnt, 1u);
                if (v == ENC_CTAS - 1) {
                    atomicExch(&g_bar_cnt, 0u);
                    atomicAdd(&g_bar_rel, 1u);
                }
                while (atomicAdd(&g_bar_rel, 0u) < (unsigned)(t + 1)) {}
            }
            __syncthreads();
        }
    }
}

// ---------------- fused decoder GRU step (per-launch, pipelined) -----------
__global__ void __launch_bounds__(256, 1) dec_gru_k(
    const float* __restrict__ Wih, const float* __restrict__ bih,
    const float* __restrict__ Whh, const float* __restrict__ bhh, int par)
{
    __shared__ float Wh[12][HID];
    __shared__ float Wi[12][HID];
    const int tid = threadIdx.x;
    const int u0 = blockIdx.x * 4;

    for (int idx = tid; idx < 12 * HID; idx += 256) {
        int r = idx >> 9, k = idx & 511;
        int g = r >> 2, ui = r & 3;
        size_t wrow = (size_t)(g * HID + u0 + ui) * HID + k;
        Wh[r][k] = Whh[wrow];
        Wi[r][k] = Wih[wrow];
    }
    const int b  = tid & 63;
    const int ui = tid >> 6;
    const int u  = u0 + ui;
    const float bhR = bhh[u], bhZ = bhh[HID + u], bhN = bhh[2 * HID + u];
    float iR = bih[u], iZ = bih[HID + u], iN = bih[2 * HID + u];
    float hR = 0.f, hZ = 0.f, hN = 0.f;
    __syncthreads();

    const float* hin = par ? g_hB : g_hA;
    float* hout      = par ? g_hA : g_hB;

    float hv[16], ev[16];
#pragma unroll
    for (int kk = 0; kk < 16; kk++) {
        hv[kk] = __ldg(hin  + kk * 64 + b);
        ev[kk] = __ldg(g_eT + kk * 64 + b);
    }

#pragma unroll 2
    for (int k0 = 0; k0 < HID; k0 += 16) {
        float hv2[16], ev2[16];
        const int kn = (k0 + 16 < HID) ? (k0 + 16) : 0;
#pragma unroll
        for (int kk = 0; kk < 16; kk++) {
            hv2[kk] = __ldg(hin  + (kn + kk) * 64 + b);
            ev2[kk] = __ldg(g_eT + (kn + kk) * 64 + b);
        }
        const float4* wr = (const float4*)&Wh[ui][k0];
        const float4* wz = (const float4*)&Wh[4 + ui][k0];
        const float4* wn = (const float4*)&Wh[8 + ui][k0];
        const float4* vr = (const float4*)&Wi[ui][k0];
        const float4* vz = (const float4*)&Wi[4 + ui][k0];
        const float4* vn = (const float4*)&Wi[8 + ui][k0];
#pragma unroll
        for (int q = 0; q < 4; q++) {
            float4 r4 = wr[q], z4 = wz[q], n4 = wn[q];
            float4 s4 = vr[q], t4 = vz[q], u4 = vn[q];
            float hw0 = hv[q*4+0], hw1 = hv[q*4+1], hw2 = hv[q*4+2], hw3 = hv[q*4+3];
            float ew0 = ev[q*4+0], ew1 = ev[q*4+1], ew2 = ev[q*4+2], ew3 = ev[q*4+3];
            hR = fmaf(hw0, r4.x, hR); hR = fmaf(hw1, r4.y, hR);
            hR = fmaf(hw2, r4.z, hR); hR = fmaf(hw3, r4.w, hR);
            hZ = fmaf(hw0, z4.x, hZ); hZ = fmaf(hw1, z4.y, hZ);
            hZ = fmaf(hw2, z4.z, hZ); hZ = fmaf(hw3, z4.w, hZ);
            hN = fmaf(hw0, n4.x, hN); hN = fmaf(hw1, n4.y, hN);
            hN = fmaf(hw2, n4.z, hN); hN = fmaf(hw3, n4.w, hN);
            iR = fmaf(ew0, s4.x, iR); iR = fmaf(ew1, s4.y, iR);
            iR = fmaf(ew2, s4.z, iR); iR = fmaf(ew3, s4.w, iR);
            iZ = fmaf(ew0, t4.x, iZ); iZ = fmaf(ew1, t4.y, iZ);
            iZ = fmaf(ew2, t4.z, iZ); iZ = fmaf(ew3, t4.w, iZ);
            iN = fmaf(ew0, u4.x, iN); iN = fmaf(ew1, u4.y, iN);
            iN = fmaf(ew2, u4.z, iN); iN = fmaf(ew3, u4.w, iN);
        }
#pragma unroll
        for (int kk = 0; kk < 16; kk++) { hv[kk] = hv2[kk]; ev[kk] = ev2[kk]; }
    }

    float r = 1.f / (1.f + expf(-(iR + bhR + hR)));
    float z = 1.f / (1.f + expf(-(iZ + bhZ + hZ)));
    float n = tanhf(iN + r * (bhN + hN));
    float hp = hin[(size_t)u * 64 + b];
    float hn = (1.f - z) * n + z * hp;
    hout[(size_t)u * 64 + b] = hn;

    // 3-way bf16 split for the mma logits GEMM, stored m-major [b][k]
    unsigned short s1 = f2bf(hn);
    float r1 = hn - bf2f(s1);
    unsigned short s2 = f2bf(r1);
    float r2 = r1 - bf2f(s2);
    unsigned short s3 = f2bf(r2);
    g_h1[(size_t)b * HID + u] = s1;
    g_h2[(size_t)b * HID + u] = s2;
    g_h3[(size_t)b * HID + u] = s3;
}

// ---------------- mma.sync logits GEMM + bias + argmax ---------------------
// D[64, 256] per CTA; 6 split-plane passes: h1W1+h2W1+h3W1+h1W2+h2W2+h1W3.
// cp.async double-buffered K chunks of 32; 80B smem row stride (bank-safe).
__global__ void __launch_bounds__(256, 1) logits_mma_k(
    const float* __restrict__ bias, float* __restrict__ out)
{
    extern __shared__ __align__(128) char smem[];
    const int tid = threadIdx.x, lane = tid & 31, w = tid >> 5;
    const int nblk = blockIdx.x * LG_NT;
    const int g = lane >> 2, q4 = (lane & 3) * 4;

    float c[4][4][4];
#pragma unroll
    for (int i = 0; i < 4; i++)
#pragma unroll
        for (int j = 0; j < 4; j++)
#pragma unroll
            for (int e = 0; e < 4; e++) c[i][j][e] = 0.f;

    const unsigned short* Wp0 = g_W1;
    const unsigned short* Wp1 = g_W2;
    const unsigned short* Wp2 = g_W3;
    const unsigned short* Hp0 = g_h1;
    const unsigned short* Hp1 = g_h2;
    const unsigned short* Hp2 = g_h3;

#define LG_ISSUE(kc) do {                                                      \
    char* buf = smem + (size_t)((kc) & 1) * SBUF;                              \
    for (int i = tid; i < 3840; i += 256) {                                    \
        const unsigned short* src; char* dst;                                  \
        if (i < 3072) {                                                        \
            int p = i >> 10, rr = (i >> 2) & 255, q = i & 3;                   \
            const unsigned short* wp = (p == 0) ? Wp0 : (p == 1) ? Wp1 : Wp2;  \
            src = wp + (size_t)(nblk + rr) * HID + (kc) * KC + q * 8;          \
            dst = buf + (p * 256 + rr) * ROWB + q * 16;                        \
        } else {                                                               \
            int jj = i - 3072;                                                 \
            int p = jj >> 8, rr = (jj >> 2) & 63, q = jj & 3;                  \
            const unsigned short* hp = (p == 0) ? Hp0 : (p == 1) ? Hp1 : Hp2;  \
            src = hp + (size_t)rr * HID + (kc) * KC + q * 8;                   \
            dst = buf + A_OFF + (p * 64 + rr) * ROWB + q * 16;                 \
        }                                                                      \
        uint32_t d32 = smem_u32(dst);                                          \
        asm volatile("cp.async.cg.shared.global [%0], [%1], 16;"               \
                     :: "r"(d32), "l"(src));                                   \
    }                                                                          \
    asm volatile("cp.async.commit_group;");                                    \
} while (0)

    LG_ISSUE(0);
    // (pB, pA) pairs
    const int PB[6] = {0, 0, 0, 1, 1, 2};
    const int PA[6] = {0, 1, 2, 0, 1, 0};

#pragma unroll 1
    for (int kc = 0; kc < 16; kc++) {
        if (kc < 15) {
            LG_ISSUE(kc + 1);
            asm volatile("cp.async.wait_group 1;");
        } else {
            asm volatile("cp.async.wait_group 0;");
        }
        __syncthreads();
        const char* buf = smem + (size_t)(kc & 1) * SBUF;
#pragma unroll
        for (int k16 = 0; k16 < 2; k16++) {
            const int kb = k16 * 32 + q4;
#pragma unroll
            for (int pr = 0; pr < 6; pr++) {
                const int pB = PB[pr], pA = PA[pr];
                uint32_t b0[4], b1[4];
#pragma unroll
                for (int nt = 0; nt < 4; nt++) {
                    const char* bp = buf + (size_t)(pB * 256 + w * 32 + nt * 8 + g) * ROWB + kb;
                    b0[nt] = *(const uint32_t*)bp;
                    b1[nt] = *(const uint32_t*)(bp + 16);
                }
#pragma unroll
                for (int mt = 0; mt < 4; mt++) {
                    const char* ap = buf + A_OFF + (size_t)(pA * 64 + mt * 16 + g) * ROWB + kb;
                    uint32_t a0 = *(const uint32_t*)ap;
                    uint32_t a1 = *(const uint32_t*)(ap + 8 * ROWB);
                    uint32_t a2 = *(const uint32_t*)(ap + 16);
                    uint32_t a3 = *(const uint32_t*)(ap + 8 * ROWB + 16);
#pragma unroll
                    for (int nt = 0; nt < 4; nt++)
                        MMA16816(c[mt][nt], a0, a1, a2, a3, b0[nt], b1[nt]);
                }
            }
        }
        __syncthreads();
    }
#undef LG_ISSUE

    // epilogue: bias, store, per-row argmax (packed-key atomicMax)
#pragma unroll
    for (int mt = 0; mt < 4; mt++) {
        const int m0 = mt * 16 + g, m1 = m0 + 8;
        unsigned long long key0 = 0ull, key1 = 0ull;
#pragma unroll
        for (int nt = 0; nt < 4; nt++) {
            const int col = nblk + w * 32 + nt * 8 + (lane & 3) * 2;
            const float bb0 = bias[col], bb1 = bias[col + 1];
            float v00 = c[mt][nt][0] + bb0, v01 = c[mt][nt][1] + bb1;
            float v10 = c[mt][nt][2] + bb0, v11 = c[mt][nt][3] + bb1;
            *(float2*)(out + (size_t)m0 * VOC + col) = make_float2(v00, v01);
            *(float2*)(out + (size_t)m1 * VOC + col) = make_float2(v10, v11);
            unsigned long long k00 = pack_key(v00, col);
            unsigned long long k01 = pack_key(v01, col + 1);
            unsigned long long k10 = pack_key(v10, col);
            unsigned long long k11 = pack_key(v11, col + 1);
            if (k00 > key0) key0 = k00;
            if (k01 > key0) key0 = k01;
            if (k10 > key1) key1 = k10;
            if (k11 > key1) key1 = k11;
        }
        // reduce over the 4 lanes covering the same rows (lane bits 0-1)
#pragma unroll
        for (int d = 1; d < 4; d <<= 1) {
            unsigned long long o0 = __shfl_xor_sync(0xFFFFFFFFu, key0, d);
            unsigned long long o1 = __shfl_xor_sync(0xFFFFFFFFu, key1, d);
            if (o0 > key0) key0 = o0;
            if (o1 > key1) key1 = o1;
        }
        if ((lane & 3) == 0) {
            atomicMax(&g_amax[m0], key0);
            atomicMax(&g_amax[m1], key1);
        }
    }
}

// ---------------- argmax finalize + next-token embedding gather -----------
__global__ void k_fin_gather(const float* __restrict__ emb_dec) {
    int b = blockIdx.x;
    __shared__ int stok;
    if (threadIdx.x == 0) {
        unsigned long long key = g_amax[b];
        stok = (int)(0xFFFFFFFFu - (unsigned)(key & 0xFFFFFFFFull));
        g_amax[b] = 0ull;
    }
    __syncthreads();
    const float* src = emb_dec + (size_t)stok * HID;
    for (int k = threadIdx.x; k < HID; k += 128)
        g_eT[(size_t)k * 64 + b] = src[k];
}

// ---------------- host orchestration --------------------------------------
extern "C" void kernel_launch(void* const* d_in, const int* in_sizes, int n_in,
                              void* d_out, int out_size) {
    const int*   batch_X = (const int*)d_in[0];
    const int*   lengths = (const int*)d_in[1];
    const float* emb_enc = (const float*)d_in[3];
    const float* Wih_e   = (const float*)d_in[4];
    const float* Whh_e   = (const float*)d_in[5];
    const float* bih_e   = (const float*)d_in[6];
    const float* bhh_e   = (const float*)d_in[7];
    const float* emb_dec = (const float*)d_in[8];
    const float* Wih_d   = (const float*)d_in[9];
    const float* Whh_d   = (const float*)d_in[10];
    const float* bih_d   = (const float*)d_in[11];
    const float* bhh_d   = (const float*)d_in[12];
    const float* Wout    = (const float*)d_in[13];
    const float* bout    = (const float*)d_in[14];
    float* out = (float*)d_out;
    const int steps = out_size / (BSZ * VOC);   // 32

    (void)in_sizes; (void)n_in;

    cudaFuncSetAttribute(logits_mma_k,
                         cudaFuncAttributeMaxDynamicSharedMemorySize, LG_SMEM);

    k_init<<<128, 256>>>(emb_dec);
    k_wsplit<<<(VOC * HID / 4 + 255) / 256, 256>>>(Wout);

    // encoder input pre-GEMM: all timesteps at once (8192 x 1536, K=512)
    sgemm0_k<<<dim3(G3H / 128, (TLEN * BSZ) / 64), 256>>>(
        emb_enc, batch_X, Wih_e, bih_e);

    // encoder recurrence: single persistent kernel, 128 steps internally
    enc_persist_k<<<ENC_CTAS, 256>>>(Whh_e, bhh_e, lengths);
    // final hidden ends in g_hA (t=127 writes g_hA)

    // decoder greedy loop
    for (int s = 0; s < steps; s++) {
        dec_gru_k<<<HID / 4, 256>>>(Wih_d, bih_d, Whh_d, bhh_d, s & 1);
        logits_mma_k<<<LG_CTAS, 256, LG_SMEM>>>(
            bout, out + (size_t)s * BSZ * VOC);
        if (s < steps - 1) k_fin_gather<<<BSZ, 128>>>(emb_dec);
    }
}

// round 9
// speedup vs baseline: 2.9269x; 1.2158x over previous
#include <cuda_runtime.h>
#include <cuda_fp16.h>
#include <math.h>
#include <stdint.h>

#define HID 512
#define BSZ 64
#define TLEN 128
#define VOC 32000
#define G3H 1536
#define ENC_CTAS 128

// scaling for fp16 split planes (powers of 2: exact)
#define SCL_MAIN 32.0f
#define SCL_RES  64.0f
#define INV_MAIN (1.0f / 1024.0f)
#define INV_RES  (1.0f / 65536.0f)

// logits GEMM tiling (fp16 2-way split, 3 explicit passes)
#define LG_NT 256
#define LG_CTAS (VOC / LG_NT)     // 125
#define KC 32
#define ROWB 80
#define B_ROWS (2 * LG_NT)        // 512
#define A_ROWS (2 * BSZ)          // 128
#define SBUF ((B_ROWS + A_ROWS) * ROWB)   // 51200
#define A_OFF (B_ROWS * ROWB)             // 40960
#define LG_SMEM (2 * SBUF)                // 102400

// ---------------- scratch ----------------
__device__ float g_gi[TLEN * G3H * BSZ];
__device__ float g_hA[HID * BSZ];
__device__ float g_hB[HID * BSZ];
__device__ float g_eT[HID * BSZ];
__device__ __align__(16) unsigned short g_W1[VOC * HID];
__device__ __align__(16) unsigned short g_W2[VOC * HID];
__device__ __align__(16) unsigned short g_h1[BSZ * HID];
__device__ __align__(16) unsigned short g_h2[BSZ * HID];
__device__ unsigned long long g_amax[BSZ];
__device__ unsigned g_bar_cnt;
__device__ unsigned g_bar_rel;

__device__ __forceinline__ unsigned ordered_f32(float f) {
    unsigned u = __float_as_uint(f);
    return (u & 0x80000000u) ? ~u : (u | 0x80000000u);
}
__device__ __forceinline__ unsigned short f2h(float x) {
    __half t = __float2half_rn(x);
    return *(unsigned short*)&t;
}
__device__ __forceinline__ float h2f(unsigned short u) {
    __half t = *(__half*)&u;
    return __half2float(t);
}
__device__ __forceinline__ uint32_t smem_u32(const void* p) {
    uint32_t a;
    asm("{ .reg .u64 t; cvta.to.shared.u64 t, %1; cvt.u32.u64 %0, t; }"
        : "=r"(a) : "l"(p));
    return a;
}
__device__ __forceinline__ unsigned long long pack_key(float v, int idx) {
    return ((unsigned long long)ordered_f32(v) << 32) |
           (unsigned long long)(0xFFFFFFFFu - (unsigned)idx);
}

#define MMA16816(C, A0, A1, A2, A3, B0, B1) \
    asm volatile("mma.sync.aligned.m16n8k16.row.col.f32.f16.f16.f32 " \
        "{%0,%1,%2,%3}, {%4,%5,%6,%7}, {%8,%9}, {%0,%1,%2,%3};" \
        : "+f"((C)[0]), "+f"((C)[1]), "+f"((C)[2]), "+f"((C)[3]) \
        : "r"(A0), "r"(A1), "r"(A2), "r"(A3), "r"(B0), "r"(B1))

// ---------------- init ----------------------------------------------------
__global__ void k_init(const float* __restrict__ emb_dec) {
    int idx = blockIdx.x * blockDim.x + threadIdx.x;
    if (idx < HID * BSZ) {
        g_hA[idx] = 0.f;
        g_eT[idx] = emb_dec[2 * HID + (idx >> 6)];     // BOS embedding, transposed
    }
    if (idx < BSZ) g_amax[idx] = 0ull;
    if (idx == 0) { g_bar_cnt = 0u; g_bar_rel = 0u; }
}

// ---------------- Wout -> scaled 2-way fp16 split (device refs only) ------
__global__ void k_wsplit2(const float* __restrict__ W) {
    size_t i = ((size_t)blockIdx.x * 256 + threadIdx.x) * 4;
    if (i >= (size_t)VOC * HID) return;
    float4 v = *(const float4*)(W + i);
    float a[4] = {v.x, v.y, v.z, v.w};
#pragma unroll
    for (int j = 0; j < 4; j++) {
        float xs = a[j] * SCL_MAIN;
        unsigned short s1 = f2h(xs);
        unsigned short s2 = f2h((xs - h2f(s1)) * SCL_RES);
        g_W1[i + j] = s1; g_W2[i + j] = s2;
    }
}

// ---------------- SGEMM: encoder input pre-GEMM (proven fp32) -------------
__global__ void __launch_bounds__(256) sgemm0_k(
    const float* __restrict__ Asrc, const int* __restrict__ tokens,
    const float* __restrict__ W, const float* __restrict__ bias)
{
    __shared__ float As[32][68];
    __shared__ float Bs[32][132];
    const int tid = threadIdx.x;
    const int tx = tid & 15, ty = tid >> 4;
    const int nblk = blockIdx.x * 128;
    const int mblk = blockIdx.y * 64;

    const int c4a = tid & 7, rowa = tid >> 3;
    const int c4b = tid & 7, rowb = tid >> 3;

    const int grow0 = tokens[mblk + rowa];
    const int grow1 = tokens[mblk + rowa + 32];
    const float* Wb = W + (size_t)nblk * HID;

    float acc[4][8];
#pragma unroll
    for (int i = 0; i < 4; i++)
#pragma unroll
        for (int j = 0; j < 8; j++) acc[i][j] = 0.f;

    float4 aR0, aR1, bR0, bR1, bR2, bR3;

#define LDG_TILE(k0) do {                                                     \
    aR0 = *(const float4*)(Asrc + (size_t)grow0 * HID + (k0) + c4a * 4);      \
    aR1 = *(const float4*)(Asrc + (size_t)grow1 * HID + (k0) + c4a * 4);      \
    bR0 = *(const float4*)(Wb + (size_t)(rowb      ) * HID + (k0) + c4b * 4); \
    bR1 = *(const float4*)(Wb + (size_t)(rowb +  32) * HID + (k0) + c4b * 4); \
    bR2 = *(const float4*)(Wb + (size_t)(rowb +  64) * HID + (k0) + c4b * 4); \
    bR3 = *(const float4*)(Wb + (size_t)(rowb +  96) * HID + (k0) + c4b * 4); \
} while (0)

#define STS_TILE() do {                                                       \
    As[c4a*4+0][rowa] = aR0.x; As[c4a*4+1][rowa] = aR0.y;                     \
    As[c4a*4+2][rowa] = aR0.z; As[c4a*4+3][rowa] = aR0.w;                     \
    As[c4a*4+0][rowa+32] = aR1.x; As[c4a*4+1][rowa+32] = aR1.y;               \
    As[c4a*4+2][rowa+32] = aR1.z; As[c4a*4+3][rowa+32] = aR1.w;               \
    Bs[c4b*4+0][rowb   ] = bR0.x; Bs[c4b*4+1][rowb   ] = bR0.y;               \
    Bs[c4b*4+2][rowb   ] = bR0.z; Bs[c4b*4+3][rowb   ] = bR0.w;               \
    Bs[c4b*4+0][rowb+32] = bR1.x; Bs[c4b*4+1][rowb+32] = bR1.y;               \
    Bs[c4b*4+2][rowb+32] = bR1.z; Bs[c4b*4+3][rowb+32] = bR1.w;               \
    Bs[c4b*4+0][rowb+64] = bR2.x; Bs[c4b*4+1][rowb+64] = bR2.y;               \
    Bs[c4b*4+2][rowb+64] = bR2.z; Bs[c4b*4+3][rowb+64] = bR2.w;               \
    Bs[c4b*4+0][rowb+96] = bR3.x; Bs[c4b*4+1][rowb+96] = bR3.y;               \
    Bs[c4b*4+2][rowb+96] = bR3.z; Bs[c4b*4+3][rowb+96] = bR3.w;               \
} while (0)

    LDG_TILE(0);
#pragma unroll 1
    for (int kt = 0; kt < 16; kt++) {
        __syncthreads();
        STS_TILE();
        __syncthreads();
        if (kt < 15) { LDG_TILE((kt + 1) * 32); }
#pragma unroll
        for (int k = 0; k < 32; k++) {
            float4 a  = *(const float4*)&As[k][ty * 4];
            float4 b0 = *(const float4*)&Bs[k][tx * 4];
            float4 b1 = *(const float4*)&Bs[k][64 + tx * 4];
            float av[4] = {a.x, a.y, a.z, a.w};
            float bv[8] = {b0.x, b0.y, b0.z, b0.w, b1.x, b1.y, b1.z, b1.w};
#pragma unroll
            for (int i = 0; i < 4; i++)
#pragma unroll
                for (int j = 0; j < 8; j++)
                    acc[i][j] = fmaf(av[i], bv[j], acc[i][j]);
        }
    }
#undef LDG_TILE
#undef STS_TILE

    const int t = blockIdx.y;
    float* gout = g_gi + ((size_t)t * G3H + nblk) * 64;
#pragma unroll
    for (int j = 0; j < 8; j++) {
        int nl = (j < 4) ? (tx * 4 + j) : (64 + tx * 4 + (j - 4));
        float bb = bias[nblk + nl];
        float4 v = make_float4(acc[0][j] + bb, acc[1][j] + bb,
                               acc[2][j] + bb, acc[3][j] + bb);
        *(float4*)(gout + (size_t)nl * 64 + ty * 4) = v;
    }
}

// ---------------- persistent encoder recurrence ----------------------------
__global__ void __launch_bounds__(256, 1) enc_persist_k(
    const float* __restrict__ Whh, const float* __restrict__ bhh,
    const int* __restrict__ lengths)
{
    __shared__ float Wh[12][HID];
    const int tid = threadIdx.x;
    const int u0 = blockIdx.x * 4;

    for (int idx = tid; idx < 12 * HID; idx += 256) {
        int r = idx >> 9, k = idx & 511;
        int g = r >> 2, ui = r & 3;
        Wh[r][k] = Whh[(size_t)(g * HID + u0 + ui) * HID + k];
    }
    const int b  = tid & 63;
    const int ui = tid >> 6;
    const int u  = u0 + ui;
    const float bR = bhh[u], bZ = bhh[HID + u], bN = bhh[2 * HID + u];
    const int len = lengths[b];
    __syncthreads();

#pragma unroll 1
    for (int t = 0; t < TLEN; t++) {
        const float* hin = (t & 1) ? g_hB : g_hA;
        float* hout      = (t & 1) ? g_hA : g_hB;
        const float* gi  = g_gi + (size_t)t * (G3H * 64);

        float giR = gi[(size_t)u * 64 + b];
        float giZ = gi[(size_t)(HID + u) * 64 + b];
        float giN = gi[(size_t)(2 * HID + u) * 64 + b];
        float hR = 0.f, hZ = 0.f, hN = 0.f;

        float hv[16];
#pragma unroll
        for (int kk = 0; kk < 16; kk++) hv[kk] = __ldcg(hin + kk * 64 + b);

#pragma unroll 2
        for (int k0 = 0; k0 < HID; k0 += 16) {
            float nv[16];
            const int kn = (k0 + 16 < HID) ? (k0 + 16) : 0;
#pragma unroll
            for (int kk = 0; kk < 16; kk++)
                nv[kk] = __ldcg(hin + (kn + kk) * 64 + b);
            const float4* wr = (const float4*)&Wh[ui][k0];
            const float4* wz = (const float4*)&Wh[4 + ui][k0];
            const float4* wn = (const float4*)&Wh[8 + ui][k0];
#pragma unroll
            for (int q = 0; q < 4; q++) {
                float4 r4 = wr[q], z4 = wz[q], n4 = wn[q];
                hR = fmaf(hv[q*4+0], r4.x, hR); hR = fmaf(hv[q*4+1], r4.y, hR);
                hR = fmaf(hv[q*4+2], r4.z, hR); hR = fmaf(hv[q*4+3], r4.w, hR);
                hZ = fmaf(hv[q*4+0], z4.x, hZ); hZ = fmaf(hv[q*4+1], z4.y, hZ);
                hZ = fmaf(hv[q*4+2], z4.z, hZ); hZ = fmaf(hv[q*4+3], z4.w, hZ);
                hN = fmaf(hv[q*4+0], n4.x, hN); hN = fmaf(hv[q*4+1], n4.y, hN);
                hN = fmaf(hv[q*4+2], n4.z, hN); hN = fmaf(hv[q*4+3], n4.w, hN);
            }
#pragma unroll
            for (int kk = 0; kk < 16; kk++) hv[kk] = nv[kk];
        }

        float r = 1.f / (1.f + expf(-(giR + bR + hR)));
        float z = 1.f / (1.f + expf(-(giZ + bZ + hZ)));
        float n = tanhf(giN + r * (bN + hN));
        float hp = __ldcg(hin + (size_t)u * 64 + b);
        float hn = (1.f - z) * n + z * hp;
        if (t >= len) hn = hp;
        hout[(size_t)u * 64 + b] = hn;

        if (t < TLEN - 1) {
            __threadfence();
            __syncthreads();
            if (tid == 0) {
                unsigned v = atomicAdd(&g_bar_cnt, 1u);
                if (v == ENC_CTAS - 1) {
                    atomicExch(&g_bar_cnt, 0u);
                    atomicAdd(&g_bar_rel, 1u);
                }
                while (atomicAdd(&g_bar_rel, 0u) < (unsigned)(t + 1)) {}
            }
            __syncthreads();
        }
    }
}

// ---------------- fused decoder GRU step ----------------------------------
__global__ void __launch_bounds__(256, 1) dec_gru_k(
    const float* __restrict__ Wih, const float* __restrict__ bih,
    const float* __restrict__ Whh, const float* __restrict__ bhh, int par)
{
    __shared__ float Wh[12][HID];
    __shared__ float Wi[12][HID];
    const int tid = threadIdx.x;
    const int u0 = blockIdx.x * 4;

    for (int idx = tid; idx < 12 * HID; idx += 256) {
        int r = idx >> 9, k = idx & 511;
        int g = r >> 2, ui = r & 3;
        size_t wrow = (size_t)(g * HID + u0 + ui) * HID + k;
        Wh[r][k] = Whh[wrow];
        Wi[r][k] = Wih[wrow];
    }
    const int b  = tid & 63;
    const int ui = tid >> 6;
    const int u  = u0 + ui;
    const float bhR = bhh[u], bhZ = bhh[HID + u], bhN = bhh[2 * HID + u];
    float iR = bih[u], iZ = bih[HID + u], iN = bih[2 * HID + u];
    float hR = 0.f, hZ = 0.f, hN = 0.f;
    __syncthreads();

    const float* hin = par ? g_hB : g_hA;
    float* hout      = par ? g_hA : g_hB;

    float hv[16], ev[16];
#pragma unroll
    for (int kk = 0; kk < 16; kk++) {
        hv[kk] = __ldg(hin  + kk * 64 + b);
        ev[kk] = __ldg(g_eT + kk * 64 + b);
    }

#pragma unroll 2
    for (int k0 = 0; k0 < HID; k0 += 16) {
        float hv2[16], ev2[16];
        const int kn = (k0 + 16 < HID) ? (k0 + 16) : 0;
#pragma unroll
        for (int kk = 0; kk < 16; kk++) {
            hv2[kk] = __ldg(hin  + (kn + kk) * 64 + b);
            ev2[kk] = __ldg(g_eT + (kn + kk) * 64 + b);
        }
        const float4* wr = (const float4*)&Wh[ui][k0];
        const float4* wz = (const float4*)&Wh[4 + ui][k0];
        const float4* wn = (const float4*)&Wh[8 + ui][k0];
        const float4* vr = (const float4*)&Wi[ui][k0];
        const float4* vz = (const float4*)&Wi[4 + ui][k0];
        const float4* vn = (const float4*)&Wi[8 + ui][k0];
#pragma unroll
        for (int q = 0; q < 4; q++) {
            float4 r4 = wr[q], z4 = wz[q], n4 = wn[q];
            float4 s4 = vr[q], t4 = vz[q], u4 = vn[q];
            float hw0 = hv[q*4+0], hw1 = hv[q*4+1], hw2 = hv[q*4+2], hw3 = hv[q*4+3];
            float ew0 = ev[q*4+0], ew1 = ev[q*4+1], ew2 = ev[q*4+2], ew3 = ev[q*4+3];
            hR = fmaf(hw0, r4.x, hR); hR = fmaf(hw1, r4.y, hR);
            hR = fmaf(hw2, r4.z, hR); hR = fmaf(hw3, r4.w, hR);
            hZ = fmaf(hw0, z4.x, hZ); hZ = fmaf(hw1, z4.y, hZ);
            hZ = fmaf(hw2, z4.z, hZ); hZ = fmaf(hw3, z4.w, hZ);
            hN = fmaf(hw0, n4.x, hN); hN = fmaf(hw1, n4.y, hN);
            hN = fmaf(hw2, n4.z, hN); hN = fmaf(hw3, n4.w, hN);
            iR = fmaf(ew0, s4.x, iR); iR = fmaf(ew1, s4.y, iR);
            iR = fmaf(ew2, s4.z, iR); iR = fmaf(ew3, s4.w, iR);
            iZ = fmaf(ew0, t4.x, iZ); iZ = fmaf(ew1, t4.y, iZ);
            iZ = fmaf(ew2, t4.z, iZ); iZ = fmaf(ew3, t4.w, iZ);
            iN = fmaf(ew0, u4.x, iN); iN = fmaf(ew1, u4.y, iN);
            iN = fmaf(ew2, u4.z, iN); iN = fmaf(ew3, u4.w, iN);
        }
#pragma unroll
        for (int kk = 0; kk < 16; kk++) { hv[kk] = hv2[kk]; ev[kk] = ev2[kk]; }
    }

    float r = 1.f / (1.f + expf(-(iR + bhR + hR)));
    float z = 1.f / (1.f + expf(-(iZ + bhZ + hZ)));
    float n = tanhf(iN + r * (bhN + hN));
    float hp = hin[(size_t)u * 64 + b];
    float hn = (1.f - z) * n + z * hp;
    hout[(size_t)u * 64 + b] = hn;

    // scaled 2-way fp16 split, stored m-major [b][k]
    float hs = hn * SCL_MAIN;
    unsigned short s1 = f2h(hs);
    unsigned short s2 = f2h((hs - h2f(s1)) * SCL_RES);
    g_h1[(size_t)b * HID + u] = s1;
    g_h2[(size_t)b * HID + u] = s2;
}

// ---------------- mma.sync logits GEMM + bias + argmax ---------------------
// 3 explicit passes: cm += h1W1 ; cr += h1W2 ; cr += h2W1.
// logit = cm/1024 + cr/65536 + bias.
__global__ void __launch_bounds__(256, 1) logits_mma_k(
    const float* __restrict__ bias, float* __restrict__ out)
{
    extern __shared__ __align__(128) char smem[];
    const int tid = threadIdx.x, lane = tid & 31, w = tid >> 5;
    const int nblk = blockIdx.x * LG_NT;
    const int g = lane >> 2, q4 = (lane & 3) * 4;

    float cm[4][4][4], cr[4][4][4];
#pragma unroll
    for (int i = 0; i < 4; i++)
#pragma unroll
        for (int j = 0; j < 4; j++)
#pragma unroll
            for (int e = 0; e < 4; e++) { cm[i][j][e] = 0.f; cr[i][j][e] = 0.f; }

#define LG_ISSUE(kc) do {                                                      \
    char* buf = smem + (size_t)((kc) & 1) * SBUF;                              \
    for (int i = tid; i < 2560; i += 256) {                                    \
        const unsigned short* src; char* dst;                                  \
        if (i < 2048) {                                                        \
            int p = i >> 10, rr = (i >> 2) & 255, q = i & 3;                   \
            const unsigned short* wp = p ? g_W2 : g_W1;                        \
            src = wp + (size_t)(nblk + rr) * HID + (kc) * KC + q * 8;          \
            dst = buf + (p * 256 + rr) * ROWB + q * 16;                        \
        } else {                                                               \
            int jj = i - 2048;                                                 \
            int p = jj >> 8, rr = (jj >> 2) & 63, q = jj & 3;                  \
            const unsigned short* hp = p ? g_h2 : g_h1;                        \
            src = hp + (size_t)rr * HID + (kc) * KC + q * 8;                   \
            dst = buf + A_OFF + (p * 64 + rr) * ROWB + q * 16;                 \
        }                                                                      \
        uint32_t d32 = smem_u32(dst);                                          \
        asm volatile("cp.async.cg.shared.global [%0], [%1], 16;"               \
                     :: "r"(d32), "l"(src));                                   \
    }                                                                          \
    asm volatile("cp.async.commit_group;");                                    \
} while (0)

    LG_ISSUE(0);

#pragma unroll 1
    for (int kc = 0; kc < 16; kc++) {
        if (kc < 15) {
            LG_ISSUE(kc + 1);
            asm volatile("cp.async.wait_group 1;");
        } else {
            asm volatile("cp.async.wait_group 0;");
        }
        __syncthreads();
        const char* buf = smem + (size_t)(kc & 1) * SBUF;
#pragma unroll
        for (int k16 = 0; k16 < 2; k16++) {
            const int kb = k16 * 32 + q4;
            // B fragments: plane0 (W1) rows [0,256), plane1 (W2) rows [256,512)
            uint32_t w1b0[4], w1b1[4], w2b0[4], w2b1[4];
#pragma unroll
            for (int nt = 0; nt < 4; nt++) {
                const char* bp0 = buf + (size_t)(      w * 32 + nt * 8 + g) * ROWB + kb;
                const char* bp1 = buf + (size_t)(256 + w * 32 + nt * 8 + g) * ROWB + kb;
                w1b0[nt] = *(const uint32_t*)bp0;
                w1b1[nt] = *(const uint32_t*)(bp0 + 16);
                w2b0[nt] = *(const uint32_t*)bp1;
                w2b1[nt] = *(const uint32_t*)(bp1 + 16);
            }
#pragma unroll
            for (int mt = 0; mt < 4; mt++) {
                // A fragments: h1 rows [0,64), h2 rows [64,128)
                const char* ap1 = buf + A_OFF + (size_t)(     mt * 16 + g) * ROWB + kb;
                const char* ap2 = buf + A_OFF + (size_t)(64 + mt * 16 + g) * ROWB + kb;
                uint32_t h1a0 = *(const uint32_t*)ap1;
                uint32_t h1a1 = *(const uint32_t*)(ap1 + 8 * ROWB);
                uint32_t h1a2 = *(const uint32_t*)(ap1 + 16);
                uint32_t h1a3 = *(const uint32_t*)(ap1 + 8 * ROWB + 16);
                uint32_t h2a0 = *(const uint32_t*)ap2;
                uint32_t h2a1 = *(const uint32_t*)(ap2 + 8 * ROWB);
                uint32_t h2a2 = *(const uint32_t*)(ap2 + 16);
                uint32_t h2a3 = *(const uint32_t*)(ap2 + 8 * ROWB + 16);
#pragma unroll
                for (int nt = 0; nt < 4; nt++) {
                    MMA16816(cm[mt][nt], h1a0, h1a1, h1a2, h1a3, w1b0[nt], w1b1[nt]);
                    MMA16816(cr[mt][nt], h1a0, h1a1, h1a2, h1a3, w2b0[nt], w2b1[nt]);
                    MMA16816(cr[mt][nt], h2a0, h2a1, h2a2, h2a3, w1b0[nt], w1b1[nt]);
                }
            }
        }
        __syncthreads();
    }
#undef LG_ISSUE

    // epilogue: combine planes, bias, store, per-row argmax
#pragma unroll
    for (int mt = 0; mt < 4; mt++) {
        const int m0 = mt * 16 + g, m1 = m0 + 8;
        unsigned long long key0 = 0ull, key1 = 0ull;
#pragma unroll
        for (int nt = 0; nt < 4; nt++) {
            const int col = nblk + w * 32 + nt * 8 + (lane & 3) * 2;
            const float bb0 = bias[col], bb1 = bias[col + 1];
            float v00 = cm[mt][nt][0] * INV_MAIN + cr[mt][nt][0] * INV_RES + bb0;
            float v01 = cm[mt][nt][1] * INV_MAIN + cr[mt][nt][1] * INV_RES + bb1;
            float v10 = cm[mt][nt][2] * INV_MAIN + cr[mt][nt][2] * INV_RES + bb0;
            float v11 = cm[mt][nt][3] * INV_MAIN + cr[mt][nt][3] * INV_RES + bb1;
            *(float2*)(out + (size_t)m0 * VOC + col) = make_float2(v00, v01);
            *(float2*)(out + (size_t)m1 * VOC + col) = make_float2(v10, v11);
            unsigned long long k00 = pack_key(v00, col);
            unsigned long long k01 = pack_key(v01, col + 1);
            unsigned long long k10 = pack_key(v10, col);
            unsigned long long k11 = pack_key(v11, col + 1);
            if (k00 > key0) key0 = k00;
            if (k01 > key0) key0 = k01;
            if (k10 > key1) key1 = k10;
            if (k11 > key1) key1 = k11;
        }
#pragma unroll
        for (int d = 1; d < 4; d <<= 1) {
            unsigned long long o0 = __shfl_xor_sync(0xFFFFFFFFu, key0, d);
            unsigned long long o1 = __shfl_xor_sync(0xFFFFFFFFu, key1, d);
            if (o0 > key0) key0 = o0;
            if (o1 > key1) key1 = o1;
        }
        if ((lane & 3) == 0) {
            atomicMax(&g_amax[m0], key0);
            atomicMax(&g_amax[m1], key1);
        }
    }
}

// ---------------- argmax finalize + next-token embedding gather -----------
__global__ void k_fin_gather(const float* __restrict__ emb_dec) {
    int b = blockIdx.x;
    __shared__ int stok;
    if (threadIdx.x == 0) {
        unsigned long long key = g_amax[b];
        stok = (int)(0xFFFFFFFFu - (unsigned)(key & 0xFFFFFFFFull));
        g_amax[b] = 0ull;
    }
    __syncthreads();
    const float* src = emb_dec + (size_t)stok * HID;
    for (int k = threadIdx.x; k < HID; k += 128)
        g_eT[(size_t)k * 64 + b] = src[k];
}

// ---------------- host orchestration --------------------------------------
extern "C" void kernel_launch(void* const* d_in, const int* in_sizes, int n_in,
                              void* d_out, int out_size) {
    const int*   batch_X = (const int*)d_in[0];
    const int*   lengths = (const int*)d_in[1];
    const float* emb_enc = (const float*)d_in[3];
    const float* Wih_e   = (const float*)d_in[4];
    const float* Whh_e   = (const float*)d_in[5];
    const float* bih_e   = (const float*)d_in[6];
    const float* bhh_e   = (const float*)d_in[7];
    const float* emb_dec = (const float*)d_in[8];
    const float* Wih_d   = (const float*)d_in[9];
    const float* Whh_d   = (const float*)d_in[10];
    const float* bih_d   = (const float*)d_in[11];
    const float* bhh_d   = (const float*)d_in[12];
    const float* Wout    = (const float*)d_in[13];
    const float* bout    = (const float*)d_in[14];
    float* out = (float*)d_out;
    const int steps = out_size / (BSZ * VOC);   // 32

    (void)in_sizes; (void)n_in;

    cudaFuncSetAttribute(logits_mma_k,
                         cudaFuncAttributeMaxDynamicSharedMemorySize, LG_SMEM);

    k_init<<<128, 256>>>(emb_dec);
    k_wsplit2<<<(VOC * HID / 4 + 255) / 256, 256>>>(Wout);

    // encoder input pre-GEMM (proven fp32 SGEMM): 8192 x 1536, K=512
    sgemm0_k<<<dim3(G3H / 128, (TLEN * BSZ) / 64), 256>>>(
        emb_enc, batch_X, Wih_e, bih_e);

    // encoder recurrence: single persistent kernel, 128 steps internally
    enc_persist_k<<<ENC_CTAS, 256>>>(Whh_e, bhh_e, lengths);
    // final hidden ends in g_hA (t=127 writes g_hA)

    // decoder greedy loop
    for (int s = 0; s < steps; s++) {
        dec_gru_k<<<HID / 4, 256>>>(Wih_d, bih_d, Whh_d, bhh_d, s & 1);
        logits_mma_k<<<LG_CTAS, 256, LG_SMEM>>>(
            bout, out + (size_t)s * BSZ * VOC);
        if (s < steps - 1) k_fin_gather<<<BSZ, 128>>>(emb_dec);
    }
}

// round 10
// speedup vs baseline: 2.9355x; 1.0030x over previous
#include <cuda_runtime.h>
#include <cuda_fp16.h>
#include <math.h>
#include <stdint.h>

#define HID 512
#define BSZ 64
#define TLEN 128
#define VOC 32000
#define G3H 1536
#define ENC_CTAS 128
#define DEC_CTAS 128
#define BOS 2

// scaling for fp16 split planes (powers of 2: exact)
#define SCL_MAIN 32.0f
#define SCL_RES  64.0f
#define INV_MAIN (1.0f / 1024.0f)
#define INV_RES  (1.0f / 65536.0f)

// logits GEMM tiling (fp16 2-way split, 3 explicit passes)
#define LG_NT 256
#define LG_CTAS (VOC / LG_NT)     // 125
#define KC 32
#define ROWB 80
#define B_ROWS (2 * LG_NT)        // 512
#define A_ROWS (2 * BSZ)          // 128
#define SBUF ((B_ROWS + A_ROWS) * ROWB)   // 51200
#define A_OFF (B_ROWS * ROWB)             // 40960
#define LG_SMEM (2 * SBUF)                // 102400

// persistent decoder smem layout: [0,24576) Wh, [24576,49152) Wi, then logits
#define DEC_WSM 49152
#define DEC_SMEM (DEC_WSM + LG_SMEM)      // 151552

// ---------------- scratch ----------------
__device__ float g_gi[TLEN * G3H * BSZ];
__device__ float g_hA[HID * BSZ];
__device__ float g_hB[HID * BSZ];
__device__ float g_eT[HID * BSZ];
__device__ __align__(16) unsigned short g_W1[VOC * HID];
__device__ __align__(16) unsigned short g_W2[VOC * HID];
__device__ __align__(16) unsigned short g_h1[BSZ * HID];
__device__ __align__(16) unsigned short g_h2[BSZ * HID];
__device__ unsigned long long g_amax2[2][BSZ];
__device__ unsigned g_bar_cnt;
__device__ unsigned g_bar_rel;
__device__ unsigned g_dcnt;
__device__ unsigned g_drel;

__device__ __forceinline__ unsigned ordered_f32(float f) {
    unsigned u = __float_as_uint(f);
    return (u & 0x80000000u) ? ~u : (u | 0x80000000u);
}
__device__ __forceinline__ unsigned short f2h(float x) {
    __half t = __float2half_rn(x);
    return *(unsigned short*)&t;
}
__device__ __forceinline__ float h2f(unsigned short u) {
    __half t = *(__half*)&u;
    return __half2float(t);
}
__device__ __forceinline__ uint32_t smem_u32(const void* p) {
    uint32_t a;
    asm("{ .reg .u64 t; cvta.to.shared.u64 t, %1; cvt.u32.u64 %0, t; }"
        : "=r"(a) : "l"(p));
    return a;
}
__device__ __forceinline__ unsigned long long pack_key(float v, int idx) {
    return ((unsigned long long)ordered_f32(v) << 32) |
           (unsigned long long)(0xFFFFFFFFu - (unsigned)idx);
}

#define MMA16816(C, A0, A1, A2, A3, B0, B1) \
    asm volatile("mma.sync.aligned.m16n8k16.row.col.f32.f16.f16.f32 " \
        "{%0,%1,%2,%3}, {%4,%5,%6,%7}, {%8,%9}, {%0,%1,%2,%3};" \
        : "+f"((C)[0]), "+f"((C)[1]), "+f"((C)[2]), "+f"((C)[3]) \
        : "r"(A0), "r"(A1), "r"(A2), "r"(A3), "r"(B0), "r"(B1))

// grid barrier for the persistent decoder (epoch-monotonic, proven pattern)
__device__ __forceinline__ void grid_bar(unsigned ep) {
    __threadfence();
    __syncthreads();
    if (threadIdx.x == 0) {
        unsigned v = atomicAdd(&g_dcnt, 1u);
        if (v == DEC_CTAS - 1) {
            atomicExch(&g_dcnt, 0u);
            __threadfence();
            atomicAdd(&g_drel, 1u);
        }
        while (atomicAdd(&g_drel, 0u) < ep) {}
    }
    __syncthreads();
}

// ---------------- init ----------------------------------------------------
__global__ void k_init(const float* __restrict__ emb_dec) {
    int idx = blockIdx.x * blockDim.x + threadIdx.x;
    if (idx < HID * BSZ) {
        g_hA[idx] = 0.f;
        g_eT[idx] = emb_dec[BOS * HID + (idx >> 6)];   // BOS embedding, transposed
    }
    if (idx < BSZ) { g_amax2[0][idx] = 0ull; g_amax2[1][idx] = 0ull; }
    if (idx == 0) { g_bar_cnt = 0u; g_bar_rel = 0u; g_dcnt = 0u; g_drel = 0u; }
}

// ---------------- Wout -> scaled 2-way fp16 split --------------------------
__global__ void k_wsplit2(const float* __restrict__ W) {
    size_t i = ((size_t)blockIdx.x * 256 + threadIdx.x) * 4;
    if (i >= (size_t)VOC * HID) return;
    float4 v = *(const float4*)(W + i);
    float a[4] = {v.x, v.y, v.z, v.w};
#pragma unroll
    for (int j = 0; j < 4; j++) {
        float xs = a[j] * SCL_MAIN;
        unsigned short s1 = f2h(xs);
        unsigned short s2 = f2h((xs - h2f(s1)) * SCL_RES);
        g_W1[i + j] = s1; g_W2[i + j] = s2;
    }
}

// ---------------- SGEMM: encoder input pre-GEMM (proven fp32) -------------
__global__ void __launch_bounds__(256) sgemm0_k(
    const float* __restrict__ Asrc, const int* __restrict__ tokens,
    const float* __restrict__ W, const float* __restrict__ bias)
{
    __shared__ float As[32][68];
    __shared__ float Bs[32][132];
    const int tid = threadIdx.x;
    const int tx = tid & 15, ty = tid >> 4;
    const int nblk = blockIdx.x * 128;
    const int mblk = blockIdx.y * 64;

    const int c4a = tid & 7, rowa = tid >> 3;
    const int c4b = tid & 7, rowb = tid >> 3;

    const int grow0 = tokens[mblk + rowa];
    const int grow1 = tokens[mblk + rowa + 32];
    const float* Wb = W + (size_t)nblk * HID;

    float acc[4][8];
#pragma unroll
    for (int i = 0; i < 4; i++)
#pragma unroll
        for (int j = 0; j < 8; j++) acc[i][j] = 0.f;

    float4 aR0, aR1, bR0, bR1, bR2, bR3;

#define LDG_TILE(k0) do {                                                     \
    aR0 = *(const float4*)(Asrc + (size_t)grow0 * HID + (k0) + c4a * 4);      \
    aR1 = *(const float4*)(Asrc + (size_t)grow1 * HID + (k0) + c4a * 4);      \
    bR0 = *(const float4*)(Wb + (size_t)(rowb      ) * HID + (k0) + c4b * 4); \
    bR1 = *(const float4*)(Wb + (size_t)(rowb +  32) * HID + (k0) + c4b * 4); \
    bR2 = *(const float4*)(Wb + (size_t)(rowb +  64) * HID + (k0) + c4b * 4); \
    bR3 = *(const float4*)(Wb + (size_t)(rowb +  96) * HID + (k0) + c4b * 4); \
} while (0)

#define STS_TILE() do {                                                       \
    As[c4a*4+0][rowa] = aR0.x; As[c4a*4+1][rowa] = aR0.y;                     \
    As[c4a*4+2][rowa] = aR0.z; As[c4a*4+3][rowa] = aR0.w;                     \
    As[c4a*4+0][rowa+32] = aR1.x; As[c4a*4+1][rowa+32] = aR1.y;               \
    As[c4a*4+2][rowa+32] = aR1.z; As[c4a*4+3][rowa+32] = aR1.w;               \
    Bs[c4b*4+0][rowb   ] = bR0.x; Bs[c4b*4+1][rowb   ] = bR0.y;               \
    Bs[c4b*4+2][rowb   ] = bR0.z; Bs[c4b*4+3][rowb   ] = bR0.w;               \
    Bs[c4b*4+0][rowb+32] = bR1.x; Bs[c4b*4+1][rowb+32] = bR1.y;               \
    Bs[c4b*4+2][rowb+32] = bR1.z; Bs[c4b*4+3][rowb+32] = bR1.w;               \
    Bs[c4b*4+0][rowb+64] = bR2.x; Bs[c4b*4+1][rowb+64] = bR2.y;               \
    Bs[c4b*4+2][rowb+64] = bR2.z; Bs[c4b*4+3][rowb+64] = bR2.w;               \
    Bs[c4b*4+0][rowb+96] = bR3.x; Bs[c4b*4+1][rowb+96] = bR3.y;               \
    Bs[c4b*4+2][rowb+96] = bR3.z; Bs[c4b*4+3][rowb+96] = bR3.w;               \
} while (0)

    LDG_TILE(0);
#pragma unroll 1
    for (int kt = 0; kt < 16; kt++) {
        __syncthreads();
        STS_TILE();
        __syncthreads();
        if (kt < 15) { LDG_TILE((kt + 1) * 32); }
#pragma unroll
        for (int k = 0; k < 32; k++) {
            float4 a  = *(const float4*)&As[k][ty * 4];
            float4 b0 = *(const float4*)&Bs[k][tx * 4];
            float4 b1 = *(const float4*)&Bs[k][64 + tx * 4];
            float av[4] = {a.x, a.y, a.z, a.w};
            float bv[8] = {b0.x, b0.y, b0.z, b0.w, b1.x, b1.y, b1.z, b1.w};
#pragma unroll
            for (int i = 0; i < 4; i++)
#pragma unroll
                for (int j = 0; j < 8; j++)
                    acc[i][j] = fmaf(av[i], bv[j], acc[i][j]);
        }
    }
#undef LDG_TILE
#undef STS_TILE

    const int t = blockIdx.y;
    float* gout = g_gi + ((size_t)t * G3H + nblk) * 64;
#pragma unroll
    for (int j = 0; j < 8; j++) {
        int nl = (j < 4) ? (tx * 4 + j) : (64 + tx * 4 + (j - 4));
        float bb = bias[nblk + nl];
        float4 v = make_float4(acc[0][j] + bb, acc[1][j] + bb,
                               acc[2][j] + bb, acc[3][j] + bb);
        *(float4*)(gout + (size_t)nl * 64 + ty * 4) = v;
    }
}

// ---------------- persistent encoder recurrence ----------------------------
__global__ void __launch_bounds__(256, 1) enc_persist_k(
    const float* __restrict__ Whh, const float* __restrict__ bhh,
    const int* __restrict__ lengths)
{
    __shared__ float Wh[12][HID];
    const int tid = threadIdx.x;
    const int u0 = blockIdx.x * 4;

    for (int idx = tid; idx < 12 * HID; idx += 256) {
        int r = idx >> 9, k = idx & 511;
        int g = r >> 2, ui = r & 3;
        Wh[r][k] = Whh[(size_t)(g * HID + u0 + ui) * HID + k];
    }
    const int b  = tid & 63;
    const int ui = tid >> 6;
    const int u  = u0 + ui;
    const float bR = bhh[u], bZ = bhh[HID + u], bN = bhh[2 * HID + u];
    const int len = lengths[b];
    __syncthreads();

#pragma unroll 1
    for (int t = 0; t < TLEN; t++) {
        const float* hin = (t & 1) ? g_hB : g_hA;
        float* hout      = (t & 1) ? g_hA : g_hB;
        const float* gi  = g_gi + (size_t)t * (G3H * 64);

        float giR = gi[(size_t)u * 64 + b];
        float giZ = gi[(size_t)(HID + u) * 64 + b];
        float giN = gi[(size_t)(2 * HID + u) * 64 + b];
        float hR = 0.f, hZ = 0.f, hN = 0.f;

        float hv[16];
#pragma unroll
        for (int kk = 0; kk < 16; kk++) hv[kk] = __ldcg(hin + kk * 64 + b);

#pragma unroll 2
        for (int k0 = 0; k0 < HID; k0 += 16) {
            float nv[16];
            const int kn = (k0 + 16 < HID) ? (k0 + 16) : 0;
#pragma unroll
            for (int kk = 0; kk < 16; kk++)
                nv[kk] = __ldcg(hin + (kn + kk) * 64 + b);
            const float4* wr = (const float4*)&Wh[ui][k0];
            const float4* wz = (const float4*)&Wh[4 + ui][k0];
            const float4* wn = (const float4*)&Wh[8 + ui][k0];
#pragma unroll
            for (int q = 0; q < 4; q++) {
                float4 r4 = wr[q], z4 = wz[q], n4 = wn[q];
                hR = fmaf(hv[q*4+0], r4.x, hR); hR = fmaf(hv[q*4+1], r4.y, hR);
                hR = fmaf(hv[q*4+2], r4.z, hR); hR = fmaf(hv[q*4+3], r4.w, hR);
                hZ = fmaf(hv[q*4+0], z4.x, hZ); hZ = fmaf(hv[q*4+1], z4.y, hZ);
                hZ = fmaf(hv[q*4+2], z4.z, hZ); hZ = fmaf(hv[q*4+3], z4.w, hZ);
                hN = fmaf(hv[q*4+0], n4.x, hN); hN = fmaf(hv[q*4+1], n4.y, hN);
                hN = fmaf(hv[q*4+2], n4.z, hN); hN = fmaf(hv[q*4+3], n4.w, hN);
            }
#pragma unroll
            for (int kk = 0; kk < 16; kk++) hv[kk] = nv[kk];
        }

        float r = 1.f / (1.f + expf(-(giR + bR + hR)));
        float z = 1.f / (1.f + expf(-(giZ + bZ + hZ)));
        float n = tanhf(giN + r * (bN + hN));
        float hp = __ldcg(hin + (size_t)u * 64 + b);
        float hn = (1.f - z) * n + z * hp;
        if (t >= len) hn = hp;
        hout[(size_t)u * 64 + b] = hn;

        if (t < TLEN - 1) {
            __threadfence();
            __syncthreads();
            if (tid == 0) {
                unsigned v = atomicAdd(&g_bar_cnt, 1u);
                if (v == ENC_CTAS - 1) {
                    atomicExch(&g_bar_cnt, 0u);
                    atomicAdd(&g_bar_rel, 1u);
                }
                while (atomicAdd(&g_bar_rel, 0u) < (unsigned)(t + 1)) {}
            }
            __syncthreads();
        }
    }
}

// ---------------- persistent decoder: all steps in one kernel --------------
// Per step: [A] token+embed gather (CTAs<64)  -> bar
//           [B] fused GRU (all CTAs, 4 units) -> bar
//           [C] fp16 3-pass logits (CTAs<125) -> bar
__global__ void __launch_bounds__(256, 1) decoder_persist_k(
    const float* __restrict__ Wih, const float* __restrict__ bih,
    const float* __restrict__ Whh, const float* __restrict__ bhh,
    const float* __restrict__ emb_dec, const float* __restrict__ bias,
    float* __restrict__ out, int steps)
{
    extern __shared__ __align__(128) char smem[];
    float (*Wh)[HID] = (float(*)[HID])(smem);
    float (*Wi)[HID] = (float(*)[HID])(smem + 24576);
    char* lsm = smem + DEC_WSM;            // logits double buffer region
    __shared__ int s_tok;

    const int tid = threadIdx.x, lane = tid & 31, w = tid >> 5;
    const int cta = blockIdx.x;
    const int u0 = cta * 4;
    unsigned ep = 0;

    // stage decoder GRU weights ONCE for all steps
    for (int idx = tid; idx < 12 * HID; idx += 256) {
        int r = idx >> 9, k = idx & 511;
        int g = r >> 2, ui = r & 3;
        size_t wrow = (size_t)(g * HID + u0 + ui) * HID + k;
        Wh[r][k] = Whh[wrow];
        Wi[r][k] = Wih[wrow];
    }
    const int b  = tid & 63;
    const int ui = tid >> 6;
    const int u  = u0 + ui;
    const float bhR = bhh[u], bhZ = bhh[HID + u], bhN = bhh[2 * HID + u];
    const float biR = bih[u], biZ = bih[HID + u], biN = bih[2 * HID + u];
    __syncthreads();

#pragma unroll 1
    for (int s = 0; s < steps; s++) {
        // ---- phase A: argmax finalize + embedding gather (s>0) ----
        if (s > 0) {
            if (cta < BSZ) {
                if (tid == 0) {
                    unsigned long long key = atomicAdd(&g_amax2[s & 1][cta], 0ull);
                    s_tok = (int)(0xFFFFFFFFu - (unsigned)(key & 0xFFFFFFFFull));
                    atomicExch(&g_amax2[s & 1][cta], 0ull);
                }
                __syncthreads();
                const float* src = emb_dec + (size_t)s_tok * HID;
#pragma unroll
                for (int k = tid; k < HID; k += 256)
                    g_eT[(size_t)k * 64 + cta] = src[k];
            }
            grid_bar(++ep);
        }

        // ---- phase B: fused GRU step ----
        {
            const float* hin = (s & 1) ? g_hB : g_hA;
            float* hout      = (s & 1) ? g_hA : g_hB;
            float iR = biR, iZ = biZ, iN = biN;
            float hR = 0.f, hZ = 0.f, hN = 0.f;

            float hv[16], ev[16];
#pragma unroll
            for (int kk = 0; kk < 16; kk++) {
                hv[kk] = __ldcg(hin  + kk * 64 + b);
                ev[kk] = __ldcg(g_eT + kk * 64 + b);
            }

#pragma unroll 2
            for (int k0 = 0; k0 < HID; k0 += 16) {
                float hv2[16], ev2[16];
                const int kn = (k0 + 16 < HID) ? (k0 + 16) : 0;
#pragma unroll
                for (int kk = 0; kk < 16; kk++) {
                    hv2[kk] = __ldcg(hin  + (kn + kk) * 64 + b);
                    ev2[kk] = __ldcg(g_eT + (kn + kk) * 64 + b);
                }
                const float4* wr = (const float4*)&Wh[ui][k0];
                const float4* wz = (const float4*)&Wh[4 + ui][k0];
                const float4* wn = (const float4*)&Wh[8 + ui][k0];
                const float4* vr = (const float4*)&Wi[ui][k0];
                const float4* vz = (const float4*)&Wi[4 + ui][k0];
                const float4* vn = (const float4*)&Wi[8 + ui][k0];
#pragma unroll
                for (int q = 0; q < 4; q++) {
                    float4 r4 = wr[q], z4 = wz[q], n4 = wn[q];
                    float4 s4 = vr[q], t4 = vz[q], u4 = vn[q];
                    float hw0 = hv[q*4+0], hw1 = hv[q*4+1], hw2 = hv[q*4+2], hw3 = hv[q*4+3];
                    float ew0 = ev[q*4+0], ew1 = ev[q*4+1], ew2 = ev[q*4+2], ew3 = ev[q*4+3];
                    hR = fmaf(hw0, r4.x, hR); hR = fmaf(hw1, r4.y, hR);
                    hR = fmaf(hw2, r4.z, hR); hR = fmaf(hw3, r4.w, hR);
                    hZ = fmaf(hw0, z4.x, hZ); hZ = fmaf(hw1, z4.y, hZ);
                    hZ = fmaf(hw2, z4.z, hZ); hZ = fmaf(hw3, z4.w, hZ);
                    hN = fmaf(hw0, n4.x, hN); hN = fmaf(hw1, n4.y, hN);
                    hN = fmaf(hw2, n4.z, hN); hN = fmaf(hw3, n4.w, hN);
                    iR = fmaf(ew0, s4.x, iR); iR = fmaf(ew1, s4.y, iR);
                    iR = fmaf(ew2, s4.z, iR); iR = fmaf(ew3, s4.w, iR);
                    iZ = fmaf(ew0, t4.x, iZ); iZ = fmaf(ew1, t4.y, iZ);
                    iZ = fmaf(ew2, t4.z, iZ); iZ = fmaf(ew3, t4.w, iZ);
                    iN = fmaf(ew0, u4.x, iN); iN = fmaf(ew1, u4.y, iN);
                    iN = fmaf(ew2, u4.z, iN); iN = fmaf(ew3, u4.w, iN);
                }
#pragma unroll
                for (int kk = 0; kk < 16; kk++) { hv[kk] = hv2[kk]; ev[kk] = ev2[kk]; }
            }

            float r = 1.f / (1.f + expf(-(iR + bhR + hR)));
            float z = 1.f / (1.f + expf(-(iZ + bhZ + hZ)));
            float n = tanhf(iN + r * (bhN + hN));
            float hp = __ldcg(hin + (size_t)u * 64 + b);
            float hn = (1.f - z) * n + z * hp;
            hout[(size_t)u * 64 + b] = hn;

            float hs = hn * SCL_MAIN;
            unsigned short s1 = f2h(hs);
            unsigned short s2 = f2h((hs - h2f(s1)) * SCL_RES);
            g_h1[(size_t)b * HID + u] = s1;
            g_h2[(size_t)b * HID + u] = s2;
        }
        grid_bar(++ep);

        // ---- phase C: logits GEMM + bias + argmax ----
        if (cta < LG_CTAS) {
            const int nblk = cta * LG_NT;
            const int g = lane >> 2, q4 = (lane & 3) * 4;
            float* ostep = out + (size_t)s * BSZ * VOC;

            float cm[4][4][4], cr[4][4][4];
#pragma unroll
            for (int i = 0; i < 4; i++)
#pragma unroll
                for (int j = 0; j < 4; j++)
#pragma unroll
                    for (int e = 0; e < 4; e++) { cm[i][j][e] = 0.f; cr[i][j][e] = 0.f; }

#define LG_ISSUE(kc) do {                                                      \
    char* buf = lsm + (size_t)((kc) & 1) * SBUF;                               \
    for (int i = tid; i < 2560; i += 256) {                                    \
        const unsigned short* src; char* dst;                                  \
        if (i < 2048) {                                                        \
            int p = i >> 10, rr = (i >> 2) & 255, q = i & 3;                   \
            const unsigned short* wp = p ? g_W2 : g_W1;                        \
            src = wp + (size_t)(nblk + rr) * HID + (kc) * KC + q * 8;          \
            dst = buf + (p * 256 + rr) * ROWB + q * 16;                        \
        } else {                                                               \
            int jj = i - 2048;                                                 \
            int p = jj >> 8, rr = (jj >> 2) & 63, q = jj & 3;                  \
            const unsigned short* hp = p ? g_h2 : g_h1;                        \
            src = hp + (size_t)rr * HID + (kc) * KC + q * 8;                   \
            dst = buf + A_OFF + (p * 64 + rr) * ROWB + q * 16;                 \
        }                                                                      \
        uint32_t d32 = smem_u32(dst);                                          \
        asm volatile("cp.async.cg.shared.global [%0], [%1], 16;"               \
                     :: "r"(d32), "l"(src));                                   \
    }                                                                          \
    asm volatile("cp.async.commit_group;");                                    \
} while (0)

            LG_ISSUE(0);
#pragma unroll 1
            for (int kc = 0; kc < 16; kc++) {
                if (kc < 15) {
                    LG_ISSUE(kc + 1);
                    asm volatile("cp.async.wait_group 1;");
                } else {
                    asm volatile("cp.async.wait_group 0;");
                }
                __syncthreads();
                const char* buf = lsm + (size_t)(kc & 1) * SBUF;
#pragma unroll
                for (int k16 = 0; k16 < 2; k16++) {
                    const int kb = k16 * 32 + q4;
                    uint32_t w1b0[4], w1b1[4], w2b0[4], w2b1[4];
#pragma unroll
                    for (int nt = 0; nt < 4; nt++) {
                        const char* bp0 = buf + (size_t)(      w * 32 + nt * 8 + g) * ROWB + kb;
                        const char* bp1 = buf + (size_t)(256 + w * 32 + nt * 8 + g) * ROWB + kb;
                        w1b0[nt] = *(const uint32_t*)bp0;
                        w1b1[nt] = *(const uint32_t*)(bp0 + 16);
                        w2b0[nt] = *(const uint32_t*)bp1;
                        w2b1[nt] = *(const uint32_t*)(bp1 + 16);
                    }
#pragma unroll
                    for (int mt = 0; mt < 4; mt++) {
                        const char* ap1 = buf + A_OFF + (size_t)(     mt * 16 + g) * ROWB + kb;
                        const char* ap2 = buf + A_OFF + (size_t)(64 + mt * 16 + g) * ROWB + kb;
                        uint32_t h1a0 = *(const uint32_t*)ap1;
                        uint32_t h1a1 = *(const uint32_t*)(ap1 + 8 * ROWB);
                        uint32_t h1a2 = *(const uint32_t*)(ap1 + 16);
                        uint32_t h1a3 = *(const uint32_t*)(ap1 + 8 * ROWB + 16);
                        uint32_t h2a0 = *(const uint32_t*)ap2;
                        uint32_t h2a1 = *(const uint32_t*)(ap2 + 8 * ROWB);
                        uint32_t h2a2 = *(const uint32_t*)(ap2 + 16);
                        uint32_t h2a3 = *(const uint32_t*)(ap2 + 8 * ROWB + 16);
#pragma unroll
                        for (int nt = 0; nt < 4; nt++) {
                            MMA16816(cm[mt][nt], h1a0, h1a1, h1a2, h1a3, w1b0[nt], w1b1[nt]);
                            MMA16816(cr[mt][nt], h1a0, h1a1, h1a2, h1a3, w2b0[nt], w2b1[nt]);
                            MMA16816(cr[mt][nt], h2a0, h2a1, h2a2, h2a3, w1b0[nt], w1b1[nt]);
                        }
                    }
                }
                __syncthreads();
            }
#undef LG_ISSUE

#pragma unroll
            for (int mt = 0; mt < 4; mt++) {
                const int m0 = mt * 16 + g, m1 = m0 + 8;
                unsigned long long key0 = 0ull, key1 = 0ull;
#pragma unroll
                for (int nt = 0; nt < 4; nt++) {
                    const int col = nblk + w * 32 + nt * 8 + (lane & 3) * 2;
                    const float bb0 = bias[col], bb1 = bias[col + 1];
                    float v00 = cm[mt][nt][0] * INV_MAIN + cr[mt][nt][0] * INV_RES + bb0;
                    float v01 = cm[mt][nt][1] * INV_MAIN + cr[mt][nt][1] * INV_RES + bb1;
                    float v10 = cm[mt][nt][2] * INV_MAIN + cr[mt][nt][2] * INV_RES + bb0;
                    float v11 = cm[mt][nt][3] * INV_MAIN + cr[mt][nt][3] * INV_RES + bb1;
                    *(float2*)(ostep + (size_t)m0 * VOC + col) = make_float2(v00, v01);
                    *(float2*)(ostep + (size_t)m1 * VOC + col) = make_float2(v10, v11);
                    unsigned long long k00 = pack_key(v00, col);
                    unsigned long long k01 = pack_key(v01, col + 1);
                    unsigned long long k10 = pack_key(v10, col);
                    unsigned long long k11 = pack_key(v11, col + 1);
                    if (k00 > key0) key0 = k00;
                    if (k01 > key0) key0 = k01;
                    if (k10 > key1) key1 = k10;
                    if (k11 > key1) key1 = k11;
                }
#pragma unroll
                for (int d = 1; d < 4; d <<= 1) {
                    unsigned long long o0 = __shfl_xor_sync(0xFFFFFFFFu, key0, d);
                    unsigned long long o1 = __shfl_xor_sync(0xFFFFFFFFu, key1, d);
                    if (o0 > key0) key0 = o0;
                    if (o1 > key1) key1 = o1;
                }
                if ((lane & 3) == 0) {
                    atomicMax(&g_amax2[(s + 1) & 1][m0], key0);
                    atomicMax(&g_amax2[(s + 1) & 1][m1], key1);
                }
            }
        }
        grid_bar(++ep);
    }
}

// ---------------- host orchestration --------------------------------------
extern "C" void kernel_launch(void* const* d_in, const int* in_sizes, int n_in,
                              void* d_out, int out_size) {
    const int*   batch_X = (const int*)d_in[0];
    const int*   lengths = (const int*)d_in[1];
    const float* emb_enc = (const float*)d_in[3];
    const float* Wih_e   = (const float*)d_in[4];
    const float* Whh_e   = (const float*)d_in[5];
    const float* bih_e   = (const float*)d_in[6];
    const float* bhh_e   = (const float*)d_in[7];
    const float* emb_dec = (const float*)d_in[8];
    const float* Wih_d   = (const float*)d_in[9];
    const float* Whh_d   = (const float*)d_in[10];
    const float* bih_d   = (const float*)d_in[11];
    const float* bhh_d   = (const float*)d_in[12];
    const float* Wout    = (const float*)d_in[13];
    const float* bout    = (const float*)d_in[14];
    float* out = (float*)d_out;
    const int steps = out_size / (BSZ * VOC);   // 32

    (void)in_sizes; (void)n_in;

    cudaFuncSetAttribute(decoder_persist_k,
                         cudaFuncAttributeMaxDynamicSharedMemorySize, DEC_SMEM);

    k_init<<<128, 256>>>(emb_dec);
    k_wsplit2<<<(VOC * HID / 4 + 255) / 256, 256>>>(Wout);

    // encoder input pre-GEMM (proven fp32 SGEMM): 8192 x 1536, K=512
    sgemm0_k<<<dim3(G3H / 128, (TLEN * BSZ) / 64), 256>>>(
        emb_enc, batch_X, Wih_e, bih_e);

    // encoder recurrence: single persistent kernel, 128 steps internally
    enc_persist_k<<<ENC_CTAS, 256>>>(Whh_e, bhh_e, lengths);
    // final hidden ends in g_hA

    // decoder: single persistent kernel, all steps internally
    decoder_persist_k<<<DEC_CTAS, 256, DEC_SMEM>>>(
        Wih_d, bih_d, Whh_d, bhh_d, emb_dec, bout, out, steps);
}

// round 11
// speedup vs baseline: 3.0558x; 1.0410x over previous
#include <cuda_runtime.h>
#include <cuda_fp16.h>
#include <math.h>
#include <stdint.h>

#define HID 512
#define BSZ 64
#define TLEN 128
#define VOC 32000
#define G3H 1536
#define ENC_CTAS 128
#define DEC_CTAS 128
#define BOS 2

// scaling for fp16 split planes (powers of 2: exact)
#define SCL_MAIN 32.0f
#define SCL_RES  64.0f
#define INV_MAIN (1.0f / 1024.0f)
#define INV_RES  (1.0f / 65536.0f)

// logits GEMM tiling (fp16 2-way split, 3 explicit passes)
#define LG_NT 256
#define LG_CTAS (VOC / LG_NT)     // 125
#define KC 32
#define ROWB 80
#define B_ROWS (2 * LG_NT)        // 512
#define A_ROWS (2 * BSZ)          // 128
#define SBUF ((B_ROWS + A_ROWS) * ROWB)   // 51200
#define A_OFF (B_ROWS * ROWB)             // 40960
#define LG_SMEM (2 * SBUF)                // 102400

// persistent decoder smem layout: [0,24576) Wh, [24576,49152) Wi, then logits
#define DEC_WSM 49152
#define DEC_SMEM (DEC_WSM + LG_SMEM)      // 151552

// pre-GEMM tiling (fp16 3-pass HMMA)
#define PG_ROWB 80
#define PG_BROWS (2 * 128)        // 256
#define PG_AROWS (2 * 64)         // 128
#define PG_SBUF ((PG_BROWS + PG_AROWS) * PG_ROWB)  // 30720
#define PG_AOFF (PG_BROWS * PG_ROWB)               // 20480
#define PG_SMEM (2 * PG_SBUF)                      // 61440

// ---------------- scratch ----------------
__device__ float g_gi[TLEN * G3H * BSZ];
__device__ float g_hA[HID * BSZ];
__device__ float g_hB[HID * BSZ];
__device__ float g_eT[HID * BSZ];
__device__ __align__(16) unsigned short g_W1[VOC * HID];
__device__ __align__(16) unsigned short g_W2[VOC * HID];
__device__ __align__(16) unsigned short g_E1[VOC * HID];
__device__ __align__(16) unsigned short g_E2[VOC * HID];
__device__ __align__(16) unsigned short g_Wi1[G3H * HID];
__device__ __align__(16) unsigned short g_Wi2[G3H * HID];
__device__ __align__(16) unsigned short g_h1[BSZ * HID];
__device__ __align__(16) unsigned short g_h2[BSZ * HID];
__device__ unsigned long long g_amax2[2][BSZ];
__device__ unsigned g_bar_cnt;
__device__ unsigned g_bar_rel;
__device__ unsigned g_dcnt;
__device__ unsigned g_drel;

__device__ __forceinline__ unsigned ordered_f32(float f) {
    unsigned u = __float_as_uint(f);
    return (u & 0x80000000u) ? ~u : (u | 0x80000000u);
}
__device__ __forceinline__ unsigned short f2h(float x) {
    __half t = __float2half_rn(x);
    return *(unsigned short*)&t;
}
__device__ __forceinline__ float h2f(unsigned short u) {
    __half t = *(__half*)&u;
    return __half2float(t);
}
__device__ __forceinline__ uint32_t smem_u32(const void* p) {
    uint32_t a;
    asm("{ .reg .u64 t; cvta.to.shared.u64 t, %1; cvt.u32.u64 %0, t; }"
        : "=r"(a) : "l"(p));
    return a;
}
__device__ __forceinline__ unsigned long long pack_key(float v, int idx) {
    return ((unsigned long long)ordered_f32(v) << 32) |
           (unsigned long long)(0xFFFFFFFFu - (unsigned)idx);
}

#define MMA16816(C, A0, A1, A2, A3, B0, B1) \
    asm volatile("mma.sync.aligned.m16n8k16.row.col.f32.f16.f16.f32 " \
        "{%0,%1,%2,%3}, {%4,%5,%6,%7}, {%8,%9}, {%0,%1,%2,%3};" \
        : "+f"((C)[0]), "+f"((C)[1]), "+f"((C)[2]), "+f"((C)[3]) \
        : "r"(A0), "r"(A1), "r"(A2), "r"(A3), "r"(B0), "r"(B1))

// grid barrier for the persistent decoder (epoch-monotonic)
__device__ __forceinline__ void grid_bar(unsigned ep) {
    __threadfence();
    __syncthreads();
    if (threadIdx.x == 0) {
        unsigned v = atomicAdd(&g_dcnt, 1u);
        if (v == DEC_CTAS - 1) {
            atomicExch(&g_dcnt, 0u);
            __threadfence();
            atomicAdd(&g_drel, 1u);
        }
        while (atomicAdd(&g_drel, 0u) < ep) {}
    }
    __syncthreads();
}

// ---------------- init ----------------------------------------------------
__global__ void k_init(const float* __restrict__ emb_dec) {
    int idx = blockIdx.x * blockDim.x + threadIdx.x;
    if (idx < HID * BSZ) {
        g_hA[idx] = 0.f;
        g_eT[idx] = emb_dec[BOS * HID + (idx >> 6)];   // BOS embedding, transposed
    }
    if (idx < BSZ) { g_amax2[0][idx] = 0ull; g_amax2[1][idx] = 0ull; }
    if (idx == 0) { g_bar_cnt = 0u; g_bar_rel = 0u; g_dcnt = 0u; g_drel = 0u; }
}

// ---------------- scaled 2-way fp16 splits (device-direct destinations) ----
__global__ void k_wsplit2(const float* __restrict__ W) {
    size_t i = ((size_t)blockIdx.x * 256 + threadIdx.x) * 4;
    if (i >= (size_t)VOC * HID) return;
    float4 v = *(const float4*)(W + i);
    float a[4] = {v.x, v.y, v.z, v.w};
#pragma unroll
    for (int j = 0; j < 4; j++) {
        float xs = a[j] * SCL_MAIN;
        unsigned short s1 = f2h(xs);
        unsigned short s2 = f2h((xs - h2f(s1)) * SCL_RES);
        g_W1[i + j] = s1; g_W2[i + j] = s2;
    }
}
__global__ void k_esplit2(const float* __restrict__ E) {
    size_t i = ((size_t)blockIdx.x * 256 + threadIdx.x) * 4;
    if (i >= (size_t)VOC * HID) return;
    float4 v = *(const float4*)(E + i);
    float a[4] = {v.x, v.y, v.z, v.w};
#pragma unroll
    for (int j = 0; j < 4; j++) {
        float xs = a[j] * SCL_MAIN;
        unsigned short s1 = f2h(xs);
        unsigned short s2 = f2h((xs - h2f(s1)) * SCL_RES);
        g_E1[i + j] = s1; g_E2[i + j] = s2;
    }
}
__global__ void k_wisplit2(const float* __restrict__ Wi) {
    size_t i = ((size_t)blockIdx.x * 256 + threadIdx.x) * 4;
    if (i >= (size_t)G3H * HID) return;
    float4 v = *(const float4*)(Wi + i);
    float a[4] = {v.x, v.y, v.z, v.w};
#pragma unroll
    for (int j = 0; j < 4; j++) {
        float xs = a[j] * SCL_MAIN;
        unsigned short s1 = f2h(xs);
        unsigned short s2 = f2h((xs - h2f(s1)) * SCL_RES);
        g_Wi1[i + j] = s1; g_Wi2[i + j] = s2;
    }
}

// ---------------- pre-GEMM via mma.sync: gi = emb[tok] @ WihT + bias -------
// grid (12, 128): 128 gate cols x one timestep tile (64 rows).
__global__ void __launch_bounds__(256, 1) pregemm_mma_k(
    const int* __restrict__ tokens, const float* __restrict__ bias)
{
    extern __shared__ __align__(128) char smem[];
    __shared__ int s_tok[64];
    const int tid = threadIdx.x, lane = tid & 31, w = tid >> 5;
    const int nblk = blockIdx.x * 128;
    const int t = blockIdx.y;
    const int g = lane >> 2, q4 = (lane & 3) * 4;

    if (tid < 64) s_tok[tid] = tokens[t * 64 + tid];
    __syncthreads();

    float cm[4][2][4], cr[4][2][4];
#pragma unroll
    for (int i = 0; i < 4; i++)
#pragma unroll
        for (int j = 0; j < 2; j++)
#pragma unroll
            for (int e = 0; e < 4; e++) { cm[i][j][e] = 0.f; cr[i][j][e] = 0.f; }

#define PG_ISSUE(kc) do {                                                      \
    char* buf = smem + (size_t)((kc) & 1) * PG_SBUF;                           \
    for (int i = tid; i < 1536; i += 256) {                                    \
        const unsigned short* src; char* dst;                                  \
        if (i < 1024) {                                                        \
            int p = i >> 9, rr = (i >> 2) & 127, q = i & 3;                    \
            const unsigned short* wp = p ? g_Wi2 : g_Wi1;                      \
            src = wp + (size_t)(nblk + rr) * HID + (kc) * KC + q * 8;          \
            dst = buf + (p * 128 + rr) * PG_ROWB + q * 16;                     \
        } else {                                                               \
            int jj = i - 1024;                                                 \
            int p = jj >> 8, rr = (jj >> 2) & 63, q = jj & 3;                  \
            const unsigned short* ep = p ? g_E2 : g_E1;                        \
            src = ep + (size_t)s_tok[rr] * HID + (kc) * KC + q * 8;            \
            dst = buf + PG_AOFF + (p * 64 + rr) * PG_ROWB + q * 16;            \
        }                                                                      \
        uint32_t d32 = smem_u32(dst);                                          \
        asm volatile("cp.async.cg.shared.global [%0], [%1], 16;"               \
                     :: "r"(d32), "l"(src));                                   \
    }                                                                          \
    asm volatile("cp.async.commit_group;");                                    \
} while (0)

    PG_ISSUE(0);

#pragma unroll 1
    for (int kc = 0; kc < 16; kc++) {
        if (kc < 15) {
            PG_ISSUE(kc + 1);
            asm volatile("cp.async.wait_group 1;");
        } else {
            asm volatile("cp.async.wait_group 0;");
        }
        __syncthreads();
        const char* buf = smem + (size_t)(kc & 1) * PG_SBUF;
#pragma unroll
        for (int k16 = 0; k16 < 2; k16++) {
            const int kb = k16 * 32 + q4;
            uint32_t w1b0[2], w1b1[2], w2b0[2], w2b1[2];
#pragma unroll
            for (int nt = 0; nt < 2; nt++) {
                const char* bp0 = buf + (size_t)(      w * 16 + nt * 8 + g) * PG_ROWB + kb;
                const char* bp1 = buf + (size_t)(128 + w * 16 + nt * 8 + g) * PG_ROWB + kb;
                w1b0[nt] = *(const uint32_t*)bp0;
                w1b1[nt] = *(const uint32_t*)(bp0 + 16);
                w2b0[nt] = *(const uint32_t*)bp1;
                w2b1[nt] = *(const uint32_t*)(bp1 + 16);
            }
#pragma unroll
            for (int mt = 0; mt < 4; mt++) {
                const char* ap1 = buf + PG_AOFF + (size_t)(     mt * 16 + g) * PG_ROWB + kb;
                const char* ap2 = buf + PG_AOFF + (size_t)(64 + mt * 16 + g) * PG_ROWB + kb;
                uint32_t e1a0 = *(const uint32_t*)ap1;
                uint32_t e1a1 = *(const uint32_t*)(ap1 + 8 * PG_ROWB);
                uint32_t e1a2 = *(const uint32_t*)(ap1 + 16);
                uint32_t e1a3 = *(const uint32_t*)(ap1 + 8 * PG_ROWB + 16);
                uint32_t e2a0 = *(const uint32_t*)ap2;
                uint32_t e2a1 = *(const uint32_t*)(ap2 + 8 * PG_ROWB);
                uint32_t e2a2 = *(const uint32_t*)(ap2 + 16);
                uint32_t e2a3 = *(const uint32_t*)(ap2 + 8 * PG_ROWB + 16);
#pragma unroll
                for (int nt = 0; nt < 2; nt++) {
                    MMA16816(cm[mt][nt], e1a0, e1a1, e1a2, e1a3, w1b0[nt], w1b1[nt]);
                    MMA16816(cr[mt][nt], e1a0, e1a1, e1a2, e1a3, w2b0[nt], w2b1[nt]);
                    MMA16816(cr[mt][nt], e2a0, e2a1, e2a2, e2a3, w1b0[nt], w1b1[nt]);
                }
            }
        }
        __syncthreads();
    }
#undef PG_ISSUE

    // epilogue: combine planes, + bias, store transposed g_gi[(t*G3H+n)*64+m]
#pragma unroll
    for (int mt = 0; mt < 4; mt++) {
        const int m0 = mt * 16 + g, m1 = m0 + 8;
#pragma unroll
        for (int nt = 0; nt < 2; nt++) {
            const int n = nblk + w * 16 + nt * 8 + (lane & 3) * 2;
            const float bb0 = bias[n], bb1 = bias[n + 1];
            float* base = g_gi + ((size_t)t * G3H + n) * 64;
            base[m0]      = cm[mt][nt][0] * INV_MAIN + cr[mt][nt][0] * INV_RES + bb0;
            base[64 + m0] = cm[mt][nt][1] * INV_MAIN + cr[mt][nt][1] * INV_RES + bb1;
            base[m1]      = cm[mt][nt][2] * INV_MAIN + cr[mt][nt][2] * INV_RES + bb0;
            base[64 + m1] = cm[mt][nt][3] * INV_MAIN + cr[mt][nt][3] * INV_RES + bb1;
        }
    }
}

// ---------------- persistent encoder recurrence (512-thr split-k) ----------
// 128 CTAs x 512 thr; thread = (b, half, ui). Each half does 256 k; half1
// dumps partials to smem, half0 combines + applies gates.
__global__ void __launch_bounds__(512, 1) enc_persist_k(
    const float* __restrict__ Whh, const float* __restrict__ bhh,
    const int* __restrict__ lengths)
{
    __shared__ float Wh[12][HID];       // 24KB
    __shared__ float part[3][4][64];    // 3KB partials from half 1
    const int tid = threadIdx.x;
    const int u0 = blockIdx.x * 4;

    for (int idx = tid; idx < 12 * HID; idx += 512) {
        int r = idx >> 9, k = idx & 511;
        int g = r >> 2, ui = r & 3;
        Wh[r][k] = Whh[(size_t)(g * HID + u0 + ui) * HID + k];
    }
    const int b    = tid & 63;
    const int half = (tid >> 6) & 1;
    const int ui   = tid >> 7;          // 0..3
    const int u    = u0 + ui;
    const int kb0  = half * 256;
    const float bR = bhh[u], bZ = bhh[HID + u], bN = bhh[2 * HID + u];
    const int len = lengths[b];
    __syncthreads();

#pragma unroll 1
    for (int t = 0; t < TLEN; t++) {
        const float* hin = (t & 1) ? g_hB : g_hA;
        float* hout      = (t & 1) ? g_hA : g_hB;
        const float* gi  = g_gi + (size_t)t * (G3H * 64);

        float hR = 0.f, hZ = 0.f, hN = 0.f;

        float hv[16];
#pragma unroll
        for (int kk = 0; kk < 16; kk++) hv[kk] = __ldcg(hin + (kb0 + kk) * 64 + b);

#pragma unroll 2
        for (int k0 = 0; k0 < 256; k0 += 16) {
            float nv[16];
            const int kn = (k0 + 16 < 256) ? (k0 + 16) : 0;
#pragma unroll
            for (int kk = 0; kk < 16; kk++)
                nv[kk] = __ldcg(hin + (kb0 + kn + kk) * 64 + b);
            const float4* wr = (const float4*)&Wh[ui][kb0 + k0];
            const float4* wz = (const float4*)&Wh[4 + ui][kb0 + k0];
            const float4* wn = (const float4*)&Wh[8 + ui][kb0 + k0];
#pragma unroll
            for (int q = 0; q < 4; q++) {
                float4 r4 = wr[q], z4 = wz[q], n4 = wn[q];
                hR = fmaf(hv[q*4+0], r4.x, hR); hR = fmaf(hv[q*4+1], r4.y, hR);
                hR = fmaf(hv[q*4+2], r4.z, hR); hR = fmaf(hv[q*4+3], r4.w, hR);
                hZ = fmaf(hv[q*4+0], z4.x, hZ); hZ = fmaf(hv[q*4+1], z4.y, hZ);
                hZ = fmaf(hv[q*4+2], z4.z, hZ); hZ = fmaf(hv[q*4+3], z4.w, hZ);
                hN = fmaf(hv[q*4+0], n4.x, hN); hN = fmaf(hv[q*4+1], n4.y, hN);
                hN = fmaf(hv[q*4+2], n4.z, hN); hN = fmaf(hv[q*4+3], n4.w, hN);
            }
#pragma unroll
            for (int kk = 0; kk < 16; kk++) hv[kk] = nv[kk];
        }

        if (half) {
            part[0][ui][b] = hR; part[1][ui][b] = hZ; part[2][ui][b] = hN;
        }
        __syncthreads();
        if (!half) {
            hR += part[0][ui][b]; hZ += part[1][ui][b]; hN += part[2][ui][b];
            float giR = gi[(size_t)u * 64 + b];
            float giZ = gi[(size_t)(HID + u) * 64 + b];
            float giN = gi[(size_t)(2 * HID + u) * 64 + b];
            float r = 1.f / (1.f + expf(-(giR + bR + hR)));
            float z = 1.f / (1.f + expf(-(giZ + bZ + hZ)));
            float n = tanhf(giN + r * (bN + hN));
            float hp = __ldcg(hin + (size_t)u * 64 + b);
            float hn = (1.f - z) * n + z * hp;
            if (t >= len) hn = hp;
            hout[(size_t)u * 64 + b] = hn;
        }

        if (t < TLEN - 1) {
            __threadfence();
            __syncthreads();
            if (tid == 0) {
                unsigned v = atomicAdd(&g_bar_cnt, 1u);
                if (v == ENC_CTAS - 1) {
                    atomicExch(&g_bar_cnt, 0u);
                    atomicAdd(&g_bar_rel, 1u);
                }
                while (atomicAdd(&g_bar_rel, 0u) < (unsigned)(t + 1)) {}
            }
            __syncthreads();
        }
    }
}

// ---------------- persistent decoder: all steps in one kernel --------------
__global__ void __launch_bounds__(256, 1) decoder_persist_k(
    const float* __restrict__ Wih, const float* __restrict__ bih,
    const float* __restrict__ Whh, const float* __restrict__ bhh,
    const float* __restrict__ emb_dec, const float* __restrict__ bias,
    float* __restrict__ out, int steps)
{
    extern __shared__ __align__(128) char smem[];
    float (*Wh)[HID] = (float(*)[HID])(smem);
    float (*Wi)[HID] = (float(*)[HID])(smem + 24576);
    char* lsm = smem + DEC_WSM;
    __shared__ int s_tok;

    const int tid = threadIdx.x, lane = tid & 31, w = tid >> 5;
    const int cta = blockIdx.x;
    const int u0 = cta * 4;
    unsigned ep = 0;

    for (int idx = tid; idx < 12 * HID; idx += 256) {
        int r = idx >> 9, k = idx & 511;
        int g = r >> 2, ui = r & 3;
        size_t wrow = (size_t)(g * HID + u0 + ui) * HID + k;
        Wh[r][k] = Whh[wrow];
        Wi[r][k] = Wih[wrow];
    }
    const int b  = tid & 63;
    const int ui = tid >> 6;
    const int u  = u0 + ui;
    const float bhR = bhh[u], bhZ = bhh[HID + u], bhN = bhh[2 * HID + u];
    const float biR = bih[u], biZ = bih[HID + u], biN = bih[2 * HID + u];
    __syncthreads();

#pragma unroll 1
    for (int s = 0; s < steps; s++) {
        // ---- phase A ----
        if (s > 0) {
            if (cta < BSZ) {
                if (tid == 0) {
                    unsigned long long key = atomicAdd(&g_amax2[s & 1][cta], 0ull);
                    s_tok = (int)(0xFFFFFFFFu - (unsigned)(key & 0xFFFFFFFFull));
                    atomicExch(&g_amax2[s & 1][cta], 0ull);
                }
                __syncthreads();
                const float* src = emb_dec + (size_t)s_tok * HID;
#pragma unroll
                for (int k = tid; k < HID; k += 256)
                    g_eT[(size_t)k * 64 + cta] = src[k];
            }
            grid_bar(++ep);
        }

        // ---- phase B: fused GRU step ----
        {
            const float* hin = (s & 1) ? g_hB : g_hA;
            float* hout      = (s & 1) ? g_hA : g_hB;
            float iR = biR, iZ = biZ, iN = biN;
            float hR = 0.f, hZ = 0.f, hN = 0.f;

            float hv[16], ev[16];
#pragma unroll
            for (int kk = 0; kk < 16; kk++) {
                hv[kk] = __ldcg(hin  + kk * 64 + b);
                ev[kk] = __ldcg(g_eT + kk * 64 + b);
            }

#pragma unroll 2
            for (int k0 = 0; k0 < HID; k0 += 16) {
                float hv2[16], ev2[16];
                const int kn = (k0 + 16 < HID) ? (k0 + 16) : 0;
#pragma unroll
                for (int kk = 0; kk < 16; kk++) {
                    hv2[kk] = __ldcg(hin  + (kn + kk) * 64 + b);
                    ev2[kk] = __ldcg(g_eT + (kn + kk) * 64 + b);
                }
                const float4* wr = (const float4*)&Wh[ui][k0];
                const float4* wz = (const float4*)&Wh[4 + ui][k0];
                const float4* wn = (const float4*)&Wh[8 + ui][k0];
                const float4* vr = (const float4*)&Wi[ui][k0];
                const float4* vz = (const float4*)&Wi[4 + ui][k0];
                const float4* vn = (const float4*)&Wi[8 + ui][k0];
#pragma unroll
                for (int q = 0; q < 4; q++) {
                    float4 r4 = wr[q], z4 = wz[q], n4 = wn[q];
                    float4 s4 = vr[q], t4 = vz[q], u4 = vn[q];
                    float hw0 = hv[q*4+0], hw1 = hv[q*4+1], hw2 = hv[q*4+2], hw3 = hv[q*4+3];
                    float ew0 = ev[q*4+0], ew1 = ev[q*4+1], ew2 = ev[q*4+2], ew3 = ev[q*4+3];
                    hR = fmaf(hw0, r4.x, hR); hR = fmaf(hw1, r4.y, hR);
                    hR = fmaf(hw2, r4.z, hR); hR = fmaf(hw3, r4.w, hR);
                    hZ = fmaf(hw0, z4.x, hZ); hZ = fmaf(hw1, z4.y, hZ);
                    hZ = fmaf(hw2, z4.z, hZ); hZ = fmaf(hw3, z4.w, hZ);
                    hN = fmaf(hw0, n4.x, hN); hN = fmaf(hw1, n4.y, hN);
                    hN = fmaf(hw2, n4.z, hN); hN = fmaf(hw3, n4.w, hN);
                    iR = fmaf(ew0, s4.x, iR); iR = fmaf(ew1, s4.y, iR);
                    iR = fmaf(ew2, s4.z, iR); iR = fmaf(ew3, s4.w, iR);
                    iZ = fmaf(ew0, t4.x, iZ); iZ = fmaf(ew1, t4.y, iZ);
                    iZ = fmaf(ew2, t4.z, iZ); iZ = fmaf(ew3, t4.w, iZ);
                    iN = fmaf(ew0, u4.x, iN); iN = fmaf(ew1, u4.y, iN);
                    iN = fmaf(ew2, u4.z, iN); iN = fmaf(ew3, u4.w, iN);
                }
#pragma unroll
                for (int kk = 0; kk < 16; kk++) { hv[kk] = hv2[kk]; ev[kk] = ev2[kk]; }
            }

            float r = 1.f / (1.f + expf(-(iR + bhR + hR)));
            float z = 1.f / (1.f + expf(-(iZ + bhZ + hZ)));
            float n = tanhf(iN + r * (bhN + hN));
            float hp = __ldcg(hin + (size_t)u * 64 + b);
            float hn = (1.f - z) * n + z * hp;
            hout[(size_t)u * 64 + b] = hn;

            float hs = hn * SCL_MAIN;
            unsigned short s1 = f2h(hs);
            unsigned short s2 = f2h((hs - h2f(s1)) * SCL_RES);
            g_h1[(size_t)b * HID + u] = s1;
            g_h2[(size_t)b * HID + u] = s2;
        }
        grid_bar(++ep);

        // ---- phase C: logits GEMM + bias + argmax ----
        if (cta < LG_CTAS) {
            const int nblk = cta * LG_NT;
            const int g = lane >> 2, q4 = (lane & 3) * 4;
            float* ostep = out + (size_t)s * BSZ * VOC;

            float cm[4][4][4], cr[4][4][4];
#pragma unroll
            for (int i = 0; i < 4; i++)
#pragma unroll
                for (int j = 0; j < 4; j++)
#pragma unroll
                    for (int e = 0; e < 4; e++) { cm[i][j][e] = 0.f; cr[i][j][e] = 0.f; }

#define LG_ISSUE(kc) do {                                                      \
    char* buf = lsm + (size_t)((kc) & 1) * SBUF;                               \
    for (int i = tid; i < 2560; i += 256) {                                    \
        const unsigned short* src; char* dst;                                  \
        if (i < 2048) {                                                        \
            int p = i >> 10, rr = (i >> 2) & 255, q = i & 3;                   \
            const unsigned short* wp = p ? g_W2 : g_W1;                        \
            src = wp + (size_t)(nblk + rr) * HID + (kc) * KC + q * 8;          \
            dst = buf + (p * 256 + rr) * ROWB + q * 16;                        \
        } else {                                                               \
            int jj = i - 2048;                                                 \
            int p = jj >> 8, rr = (jj >> 2) & 63, q = jj & 3;                  \
            const unsigned short* hp = p ? g_h2 : g_h1;                        \
            src = hp + (size_t)rr * HID + (kc) * KC + q * 8;                   \
            dst = buf + A_OFF + (p * 64 + rr) * ROWB + q * 16;                 \
        }                                                                      \
        uint32_t d32 = smem_u32(dst);                                          \
        asm volatile("cp.async.cg.shared.global [%0], [%1], 16;"               \
                     :: "r"(d32), "l"(src));                                   \
    }                                                                          \
    asm volatile("cp.async.commit_group;");                                    \
} while (0)

            LG_ISSUE(0);
#pragma unroll 1
            for (int kc = 0; kc < 16; kc++) {
                if (kc < 15) {
                    LG_ISSUE(kc + 1);
                    asm volatile("cp.async.wait_group 1;");
                } else {
                    asm volatile("cp.async.wait_group 0;");
                }
                __syncthreads();
                const char* buf = lsm + (size_t)(kc & 1) * SBUF;
#pragma unroll
                for (int k16 = 0; k16 < 2; k16++) {
                    const int kb = k16 * 32 + q4;
                    uint32_t w1b0[4], w1b1[4], w2b0[4], w2b1[4];
#pragma unroll
                    for (int nt = 0; nt < 4; nt++) {
                        const char* bp0 = buf + (size_t)(      w * 32 + nt * 8 + g) * ROWB + kb;
                        const char* bp1 = buf + (size_t)(256 + w * 32 + nt * 8 + g) * ROWB + kb;
                        w1b0[nt] = *(const uint32_t*)bp0;
                        w1b1[nt] = *(const uint32_t*)(bp0 + 16);
                        w2b0[nt] = *(const uint32_t*)bp1;
                        w2b1[nt] = *(const uint32_t*)(bp1 + 16);
                    }
#pragma unroll
                    for (int mt = 0; mt < 4; mt++) {
                        const char* ap1 = buf + A_OFF + (size_t)(     mt * 16 + g) * ROWB + kb;
                        const char* ap2 = buf + A_OFF + (size_t)(64 + mt * 16 + g) * ROWB + kb;
                        uint32_t h1a0 = *(const uint32_t*)ap1;
                        uint32_t h1a1 = *(const uint32_t*)(ap1 + 8 * ROWB);
                        uint32_t h1a2 = *(const uint32_t*)(ap1 + 16);
                        uint32_t h1a3 = *(const uint32_t*)(ap1 + 8 * ROWB + 16);
                        uint32_t h2a0 = *(const uint32_t*)ap2;
                        uint32_t h2a1 = *(const uint32_t*)(ap2 + 8 * ROWB);
                        uint32_t h2a2 = *(const uint32_t*)(ap2 + 16);
                        uint32_t h2a3 = *(const uint32_t*)(ap2 + 8 * ROWB + 16);
#pragma unroll
                        for (int nt = 0; nt < 4; nt++) {
                            MMA16816(cm[mt][nt], h1a0, h1a1, h1a2, h1a3, w1b0[nt], w1b1[nt]);
                            MMA16816(cr[mt][nt], h1a0, h1a1, h1a2, h1a3, w2b0[nt], w2b1[nt]);
                            MMA16816(cr[mt][nt], h2a0, h2a1, h2a2, h2a3, w1b0[nt], w1b1[nt]);
                        }
                    }
                }
                __syncthreads();
            }
#undef LG_ISSUE

#pragma unroll
            for (int mt = 0; mt < 4; mt++) {
                const int m0 = mt * 16 + g, m1 = m0 + 8;
                unsigned long long key0 = 0ull, key1 = 0ull;
#pragma unroll
                for (int nt = 0; nt < 4; nt++) {
                    const int col = nblk + w * 32 + nt * 8 + (lane & 3) * 2;
                    const float bb0 = bias[col], bb1 = bias[col + 1];
                    float v00 = cm[mt][nt][0] * INV_MAIN + cr[mt][nt][0] * INV_RES + bb0;
                    float v01 = cm[mt][nt][1] * INV_MAIN + cr[mt][nt][1] * INV_RES + bb1;
                    float v10 = cm[mt][nt][2] * INV_MAIN + cr[mt][nt][2] * INV_RES + bb0;
                    float v11 = cm[mt][nt][3] * INV_MAIN + cr[mt][nt][3] * INV_RES + bb1;
                    *(float2*)(ostep + (size_t)m0 * VOC + col) = make_float2(v00, v01);
                    *(float2*)(ostep + (size_t)m1 * VOC + col) = make_float2(v10, v11);
                    unsigned long long k00 = pack_key(v00, col);
                    unsigned long long k01 = pack_key(v01, col + 1);
                    unsigned long long k10 = pack_key(v10, col);
                    unsigned long long k11 = pack_key(v11, col + 1);
                    if (k00 > key0) key0 = k00;
                    if (k01 > key0) key0 = k01;
                    if (k10 > key1) key1 = k10;
                    if (k11 > key1) key1 = k11;
                }
#pragma unroll
                for (int d = 1; d < 4; d <<= 1) {
                    unsigned long long o0 = __shfl_xor_sync(0xFFFFFFFFu, key0, d);
                    unsigned long long o1 = __shfl_xor_sync(0xFFFFFFFFu, key1, d);
                    if (o0 > key0) key0 = o0;
                    if (o1 > key1) key1 = o1;
                }
                if ((lane & 3) == 0) {
                    atomicMax(&g_amax2[(s + 1) & 1][m0], key0);
                    atomicMax(&g_amax2[(s + 1) & 1][m1], key1);
                }
            }
        }
        grid_bar(++ep);
    }
}

// ---------------- host orchestration --------------------------------------
extern "C" void kernel_launch(void* const* d_in, const int* in_sizes, int n_in,
                              void* d_out, int out_size) {
    const int*   batch_X = (const int*)d_in[0];
    const int*   lengths = (const int*)d_in[1];
    const float* emb_enc = (const float*)d_in[3];
    const float* Wih_e   = (const float*)d_in[4];
    const float* Whh_e   = (const float*)d_in[5];
    const float* bih_e   = (const float*)d_in[6];
    const float* bhh_e   = (const float*)d_in[7];
    const float* emb_dec = (const float*)d_in[8];
    const float* Wih_d   = (const float*)d_in[9];
    const float* Whh_d   = (const float*)d_in[10];
    const float* bih_d   = (const float*)d_in[11];
    const float* bhh_d   = (const float*)d_in[12];
    const float* Wout    = (const float*)d_in[13];
    const float* bout    = (const float*)d_in[14];
    float* out = (float*)d_out;
    const int steps = out_size / (BSZ * VOC);   // 32

    (void)in_sizes; (void)n_in;

    cudaFuncSetAttribute(decoder_persist_k,
                         cudaFuncAttributeMaxDynamicSharedMemorySize, DEC_SMEM);
    cudaFuncSetAttribute(pregemm_mma_k,
                         cudaFuncAttributeMaxDynamicSharedMemorySize, PG_SMEM);

    k_init<<<128, 256>>>(emb_dec);
    k_wsplit2<<<(VOC * HID / 4 + 255) / 256, 256>>>(Wout);
    k_esplit2<<<(VOC * HID / 4 + 255) / 256, 256>>>(emb_enc);
    k_wisplit2<<<(G3H * HID / 4 + 255) / 256, 256>>>(Wih_e);

    // encoder input pre-GEMM on tensor cores (scaled fp16 split, 3 passes)
    pregemm_mma_k<<<dim3(G3H / 128, TLEN), 256, PG_SMEM>>>(batch_X, bih_e);

    // encoder recurrence: single persistent kernel, 128 steps internally
    enc_persist_k<<<ENC_CTAS, 512>>>(Whh_e, bhh_e, lengths);
    // final hidden ends in g_hA

    // decoder: single persistent kernel, all steps internally
    decoder_persist_k<<<DEC_CTAS, 256, DEC_SMEM>>>(
        Wih_d, bih_d, Whh_d, bhh_d, emb_dec, bout, out, steps);
}